// round 6
// baseline (speedup 1.0000x reference)
#include <cuda_runtime.h>
#include <cstdint>
#include <cstddef>

#define Bv 16
#define Tv 576
#define NHv 12
#define HDv 64
#define DMv 768
#define LDv 256

// ---------------- scratch (static device allocations; no cudaMalloc) ---------
__device__ float g_q[Bv * Tv * DMv];
__device__ float g_lat[Bv * Tv * LDv];
__device__ float g_lp2[Bv * 144 * LDv];
__device__ float g_lp4[Bv * 36 * LDv];
__device__ float g_k[Bv * Tv * DMv];
__device__ float g_v[Bv * Tv * DMv];
__device__ float g_k2[Bv * 144 * DMv];
__device__ float g_v2[Bv * 144 * DMv];
__device__ float g_k4[Bv * 36 * DMv];
__device__ float g_v4[Bv * 36 * DMv];
__device__ float g_ctx[Bv * Tv * DMv];
__device__ float g_wc[2555904];          // tf32-rounded weights
__device__ float g_xr[Bv * Tv * DMv];    // tf32-rounded x
__device__ float g_bias[5225472];        // dense bias, transposed [h][key][q]

#define B2OFF 3981312
#define B4OFF 4976640

// ---------------- helpers -----------------------------------------------------
__device__ __forceinline__ uint32_t f2tf(float f) {
    uint32_t u;
    asm("cvt.rna.tf32.f32 %0, %1;" : "=r"(u) : "f"(f));
    return u;
}

__device__ __forceinline__ void mma_tf32(float& c0, float& c1, float& c2, float& c3,
                                         uint32_t a0, uint32_t a1, uint32_t a2, uint32_t a3,
                                         uint32_t b0, uint32_t b1) {
    asm volatile(
        "mma.sync.aligned.m16n8k8.row.col.f32.tf32.tf32.f32 "
        "{%0,%1,%2,%3}, {%4,%5,%6,%7}, {%8,%9}, {%0,%1,%2,%3};"
        : "+f"(c0), "+f"(c1), "+f"(c2), "+f"(c3)
        : "r"(a0), "r"(a1), "r"(a2), "r"(a3), "r"(b0), "r"(b1));
}

__device__ __forceinline__ void cpa16(uint32_t dst, const void* src) {
    asm volatile("cp.async.cg.shared.global [%0], [%1], 16;" :: "r"(dst), "l"(src));
}
__device__ __forceinline__ void cpa16z(uint32_t dst, const void* src, int pred) {
    asm volatile(
        "{\n\t.reg .pred p;\n\tsetp.ne.b32 p, %2, 0;\n\t"
        "@p cp.async.cg.shared.global [%0], [%1], 16;\n\t"
        "@!p cp.async.cg.shared.global [%0], [%1], 16, 0;\n\t}"
        :: "r"(dst), "l"(src), "r"(pred));
}
__device__ __forceinline__ void cp_commit() { asm volatile("cp.async.commit_group;"); }
__device__ __forceinline__ void cp_wait0() { asm volatile("cp.async.wait_group 0;"); }

// ---------------- tf32 pre-rounding (weights + x) ------------------------------
struct CvtArgs {
    const float* src[10];
    float* dst[10];
    int n[10];
};
__global__ void cvtw_kernel(CvtArgs a) {
    int gid = blockIdx.x * blockDim.x + threadIdx.x;
    int stride = gridDim.x * blockDim.x;
#pragma unroll
    for (int s = 0; s < 10; s++) {
        const float* sp = a.src[s];
        float* dp = a.dst[s];
        int n = a.n[s];
        for (int i = gid; i < n; i += stride)
            dp[i] = __uint_as_float(f2tf(sp[i]));
    }
}

// ---------------- dense bias precompute: out[(h*Kseg+key)*576 + q] -------------
__global__ void bias_pre(const float* __restrict__ tbl, float* __restrict__ out,
                         int s, int gw_, int Kseg, int tw_) {
    int gid = blockIdx.x * blockDim.x + threadIdx.x;
    int total = NHv * Kseg * 576;
    if (gid >= total) return;
    int q = gid % 576;
    int rest = gid / 576;
    int key = rest % Kseg;
    int h = rest / Kseg;
    float hctr = 0.5f * (float)(s - 1);
    int khg = key / gw_, kwg = key % gw_;
    float khc = (float)(khg * s) + hctr;
    float kwc = (float)(kwg * s) + hctr;
    float qh = (float)(q / 24), qw = (float)(q % 24);
    int rh = (int)(qh - khc) + 23;
    int rw = (int)(qw - kwc) + gw_ - 1;
    out[gid] = tbl[h * 47 * tw_ + rh * tw_ + rw];
}

// ---------------- tf32 tensor-core GEMM, all-cp.async, BK=32 -------------------
__global__ __launch_bounds__(256, 2) void gemm_tc(
    const float* __restrict__ A, const float* __restrict__ Bw,
    const float* __restrict__ B2, const float* __restrict__ bias,
    float* __restrict__ C, float* __restrict__ C2,
    int M, int N, int K, int round_out) {
    if (blockIdx.z == 1) { Bw = B2; C = C2; }

    extern __shared__ uint32_t sm[];
    const int bm = blockIdx.y * 128;
    const int bn = blockIdx.x * 128;
    const int tid = threadIdx.x;
    const int lane = tid & 31;
    const int warp = tid >> 5;
    const int wm = (warp & 1) * 64;
    const int wn = (warp >> 1) * 32;
    const int g = lane >> 2;
    const int t = lane & 3;
    const int nk = K >> 5;
    uint32_t sb = (uint32_t)__cvta_generic_to_shared(sm);

    auto issue = [&](int it) {
        int buf = it & 1;
        int k0 = it << 5;
#pragma unroll
        for (int u = 0; u < 4; u++) {
            int idx = u * 256 + tid;
            int r = idx >> 3;
            int c4 = (idx & 7) << 2;
            int pred = (bm + r) < M;
            cpa16z(sb + (buf * 4608 + r * 36 + c4) * 4,
                   A + (size_t)(bm + r) * K + k0 + c4, pred);
        }
#pragma unroll
        for (int u = 0; u < 4; u++) {
            int idx = u * 256 + tid;
            int kk = idx >> 5;
            int c4 = (idx & 31) << 2;
            cpa16(sb + (9216 + buf * 4224 + kk * 132 + c4) * 4,
                  Bw + (size_t)(k0 + kk) * N + bn + c4);
        }
    };

    float c[4][4][4];
#pragma unroll
    for (int mt = 0; mt < 4; mt++)
#pragma unroll
        for (int nt = 0; nt < 4; nt++)
#pragma unroll
            for (int r = 0; r < 4; r++) c[mt][nt][r] = 0.f;

    issue(0);
    cp_commit();

    for (int it = 0; it < nk; it++) {
        cp_wait0();
        __syncthreads();
        if (it + 1 < nk) { issue(it + 1); cp_commit(); }
        const uint32_t* Ab = sm + (it & 1) * 4608;
        const uint32_t* Bb = sm + 9216 + (it & 1) * 4224;
#pragma unroll
        for (int ks = 0; ks < 4; ks++) {
            uint32_t af[4][4], bf[4][2];
#pragma unroll
            for (int mt = 0; mt < 4; mt++) {
                int r = wm + mt * 16 + g;
                af[mt][0] = Ab[r * 36 + ks * 8 + t];
                af[mt][1] = Ab[(r + 8) * 36 + ks * 8 + t];
                af[mt][2] = Ab[r * 36 + ks * 8 + t + 4];
                af[mt][3] = Ab[(r + 8) * 36 + ks * 8 + t + 4];
            }
#pragma unroll
            for (int nt = 0; nt < 4; nt++) {
                int col = wn + nt * 8 + g;
                bf[nt][0] = Bb[(ks * 8 + t) * 132 + col];
                bf[nt][1] = Bb[(ks * 8 + t + 4) * 132 + col];
            }
#pragma unroll
            for (int mt = 0; mt < 4; mt++)
#pragma unroll
                for (int nt = 0; nt < 4; nt++)
                    mma_tf32(c[mt][nt][0], c[mt][nt][1], c[mt][nt][2], c[mt][nt][3],
                             af[mt][0], af[mt][1], af[mt][2], af[mt][3],
                             bf[nt][0], bf[nt][1]);
        }
        __syncthreads();
    }

#pragma unroll
    for (int mt = 0; mt < 4; mt++) {
#pragma unroll
        for (int nt = 0; nt < 4; nt++) {
            int row0 = bm + wm + mt * 16 + g;
            int col = bn + wn + nt * 8 + t * 2;
            float b0 = bias ? bias[col] : 0.f;
            float b1 = bias ? bias[col + 1] : 0.f;
            float v0 = c[mt][nt][0] + b0, v1 = c[mt][nt][1] + b1;
            float v2 = c[mt][nt][2] + b0, v3 = c[mt][nt][3] + b1;
            if (round_out) {
                v0 = __uint_as_float(f2tf(v0)); v1 = __uint_as_float(f2tf(v1));
                v2 = __uint_as_float(f2tf(v2)); v3 = __uint_as_float(f2tf(v3));
            }
            if (row0 < M) *(float2*)(C + (size_t)row0 * N + col) = make_float2(v0, v1);
            if (row0 + 8 < M) *(float2*)(C + (size_t)(row0 + 8) * N + col) = make_float2(v2, v3);
        }
    }
}

// ---------------- exact sxs mean pooling (tf32-rounded output) ------------------
__global__ void pool_kernel(const float* __restrict__ lat, float* __restrict__ out,
                            int s, int g, int n) {
    int idx = blockIdx.x * blockDim.x + threadIdx.x;
    if (idx >= n) return;
    int c = idx & (LDv - 1);
    int rest = idx >> 8;
    int cell = rest % (g * g);
    int b = rest / (g * g);
    int gh = cell / g, gw = cell % g;
    float sum = 0.f;
    for (int i = 0; i < s; i++)
        for (int j = 0; j < s; j++)
            sum += lat[((size_t)(b * Tv) + (gh * s + i) * 24 + (gw * s + j)) * LDv + c];
    out[idx] = __uint_as_float(f2tf(sum / (float)(s * s)));
}

// ---------------- fused 3-scale tensor-core flash attention, v3 -----------------
// 128 q-rows per block, 128 threads (4 warps x 32 rows = two 16-row m-groups).
// B-fragments (K and V) shared across both m-groups; Q fragments of both
// groups hoisted to registers. Bias read from the dense precomputed table.
// smem words: Ks 2x64x68 [0,8704), Vs 2x64x72 [8704,17920), Ps 128x68 [17920,26624)
#define ATT_SMEM_WORDS 26624

__global__ __launch_bounds__(128, 2) void attn_fused(
    const float* __restrict__ qbuf,
    const float* __restrict__ k1, const float* __restrict__ v1,
    const float* __restrict__ k2, const float* __restrict__ v2,
    const float* __restrict__ k4, const float* __restrict__ v4,
    const float* __restrict__ bias, float* __restrict__ ctx) {
    extern __shared__ uint32_t smu[];
    uint32_t* Ps = smu + 17920;
    uint32_t sb = (uint32_t)__cvta_generic_to_shared(smu);

    const int b = blockIdx.z;
    const int h = blockIdx.y;
    const int q0 = blockIdx.x * 128;
    const int tid = threadIdx.x;
    const int lane = tid & 31;
    const int w = tid >> 5;
    const int g = lane >> 2;
    const int t = lane & 3;
    const int lrA0 = w * 32 + g;
    const int lrA1 = lrA0 + 8;
    const int lrB0 = lrA0 + 16;
    const int lrB1 = lrA0 + 24;

    auto issue_kv = [&](int vt) {
        const float *kb, *vb;
        int Kt, kt;
        if (vt < 9) {
            kb = k1 + (size_t)b * 576 * DMv + h * HDv;
            vb = v1 + (size_t)b * 576 * DMv + h * HDv;
            Kt = 576; kt = vt;
        } else if (vt < 12) {
            kb = k2 + (size_t)b * 144 * DMv + h * HDv;
            vb = v2 + (size_t)b * 144 * DMv + h * HDv;
            Kt = 144; kt = vt - 9;
        } else {
            kb = k4 + (size_t)b * 36 * DMv + h * HDv;
            vb = v4 + (size_t)b * 36 * DMv + h * HDv;
            Kt = 36; kt = 0;
        }
        int buf = vt & 1;
#pragma unroll
        for (int u = 0; u < 8; u++) {
            int idx = u * 128 + tid;
            int r = idx >> 4;
            int c4 = (idx & 15) << 2;
            int kg = kt * 64 + r;
            int pred = kg < Kt;
            cpa16z(sb + (buf * 4352 + r * 68 + c4) * 4,
                   kb + (size_t)kg * DMv + c4, pred);
            cpa16z(sb + (8704 + buf * 4608 + r * 72 + c4) * 4,
                   vb + (size_t)kg * DMv + c4, pred);
        }
    };

    // stage Q (128 x 64) into Ps, coalesced; clamp tail rows
    const float* qsrc = qbuf + ((size_t)(b * Tv)) * DMv + h * HDv;
#pragma unroll
    for (int u = 0; u < 16; u++) {
        int idx = u * 128 + tid;
        int r = idx >> 4;
        int c4 = (idx & 15) << 2;
        int row = q0 + r;
        if (row > Tv - 1) row = Tv - 1;
        *(float4*)((float*)&Ps[r * 68 + c4]) = *(const float4*)(qsrc + (size_t)row * DMv + c4);
    }
    issue_kv(0);
    cp_commit();
    __syncthreads();

    // hoist Q fragments for both m-groups
    uint32_t qfA[8][4], qfB[8][4];
#pragma unroll
    for (int kd = 0; kd < 8; kd++) {
        qfA[kd][0] = Ps[lrA0 * 68 + kd * 8 + t];
        qfA[kd][1] = Ps[lrA1 * 68 + kd * 8 + t];
        qfA[kd][2] = Ps[lrA0 * 68 + kd * 8 + t + 4];
        qfA[kd][3] = Ps[lrA1 * 68 + kd * 8 + t + 4];
        qfB[kd][0] = Ps[lrB0 * 68 + kd * 8 + t];
        qfB[kd][1] = Ps[lrB1 * 68 + kd * 8 + t];
        qfB[kd][2] = Ps[lrB0 * 68 + kd * 8 + t + 4];
        qfB[kd][3] = Ps[lrB1 * 68 + kd * 8 + t + 4];
    }

    float oA[8][4], oB[8][4];
#pragma unroll
    for (int nt = 0; nt < 8; nt++)
#pragma unroll
        for (int r = 0; r < 4; r++) { oA[nt][r] = 0.f; oB[nt][r] = 0.f; }
    float lA0 = 0.f, lA1 = 0.f, lB0 = 0.f, lB1 = 0.f;

    const float scl = 0.125f;
    const int qiA0 = q0 + lrA0, qiA1 = q0 + lrA1;
    const int qiB0 = q0 + lrB0, qiB1 = q0 + lrB1;
    const int qcA0 = qiA0 < Tv ? qiA0 : Tv - 1;
    const int qcA1 = qiA1 < Tv ? qiA1 : Tv - 1;
    const int qcB0 = qiB0 < Tv ? qiB0 : Tv - 1;
    const int qcB1 = qiB1 < Tv ? qiB1 : Tv - 1;
    float* cA0 = ctx + ((size_t)(b * Tv + qcA0)) * DMv + h * HDv;
    float* cA1 = ctx + ((size_t)(b * Tv + qcA1)) * DMv + h * HDv;
    float* cB0 = ctx + ((size_t)(b * Tv + qcB0)) * DMv + h * HDv;
    float* cB1 = ctx + ((size_t)(b * Tv + qcB1)) * DMv + h * HDv;

    for (int vt = 0; vt < 13; vt++) {
        int seg, Kt, kt;
        const float* bb;
        if (vt < 9)       { seg = 0; Kt = 576; kt = vt;     bb = bias + (size_t)h * 576 * 576; }
        else if (vt < 12) { seg = 1; Kt = 144; kt = vt - 9; bb = bias + B2OFF + (size_t)h * 144 * 576; }
        else              { seg = 2; Kt = 36;  kt = 0;      bb = bias + B4OFF + (size_t)h * 36 * 576; }
        const int buf = vt & 1;

        cp_wait0();
        __syncthreads();
        if (vt + 1 < 13) { issue_kv(vt + 1); cp_commit(); }

        const uint32_t* Ks = smu + buf * 4352;
        const uint32_t* Vs = smu + 8704 + buf * 4608;

        // ---- S = Q K^T, both m-groups sharing B fragments ----
        float sfA[8][4], sfB[8][4];
#pragma unroll
        for (int nt = 0; nt < 8; nt++)
#pragma unroll
            for (int r = 0; r < 4; r++) { sfA[nt][r] = 0.f; sfB[nt][r] = 0.f; }
#pragma unroll
        for (int kd = 0; kd < 8; kd++) {
#pragma unroll
            for (int nt = 0; nt < 8; nt++) {
                uint32_t b0 = Ks[(nt * 8 + g) * 68 + kd * 8 + t];
                uint32_t b1 = Ks[(nt * 8 + g) * 68 + kd * 8 + t + 4];
                mma_tf32(sfA[nt][0], sfA[nt][1], sfA[nt][2], sfA[nt][3],
                         qfA[kd][0], qfA[kd][1], qfA[kd][2], qfA[kd][3], b0, b1);
                mma_tf32(sfB[nt][0], sfB[nt][1], sfB[nt][2], sfB[nt][3],
                         qfB[kd][0], qfB[kd][1], qfB[kd][2], qfB[kd][3], b0, b1);
            }
        }

        // ---- bias + exp + P store, per group ----
#pragma unroll
        for (int nt = 0; nt < 8; nt++) {
#pragma unroll
            for (int cc = 0; cc < 2; cc++) {
                int lc = nt * 8 + t * 2 + cc;
                int kg = kt * 64 + lc;
                float pA0 = 0.f, pA1 = 0.f, pB0 = 0.f, pB1 = 0.f;
                if (kg < Kt) {
                    const float* bp = bb + (size_t)kg * 576;
                    pA0 = __expf(sfA[nt][cc] * scl + __ldg(bp + qcA0));
                    pA1 = __expf(sfA[nt][cc + 2] * scl + __ldg(bp + qcA1));
                    pB0 = __expf(sfB[nt][cc] * scl + __ldg(bp + qcB0));
                    pB1 = __expf(sfB[nt][cc + 2] * scl + __ldg(bp + qcB1));
                }
                lA0 += pA0; lA1 += pA1; lB0 += pB0; lB1 += pB1;
                Ps[lrA0 * 68 + lc] = f2tf(pA0);
                Ps[lrA1 * 68 + lc] = f2tf(pA1);
                Ps[lrB0 * 68 + lc] = f2tf(pB0);
                Ps[lrB1 * 68 + lc] = f2tf(pB1);
            }
        }
        __syncwarp();

        // ---- O += P V, both m-groups sharing B fragments ----
#pragma unroll
        for (int ks = 0; ks < 8; ks++) {
            uint32_t aA0 = Ps[lrA0 * 68 + ks * 8 + t];
            uint32_t aA1 = Ps[lrA1 * 68 + ks * 8 + t];
            uint32_t aA2 = Ps[lrA0 * 68 + ks * 8 + t + 4];
            uint32_t aA3 = Ps[lrA1 * 68 + ks * 8 + t + 4];
            uint32_t aB0 = Ps[lrB0 * 68 + ks * 8 + t];
            uint32_t aB1 = Ps[lrB1 * 68 + ks * 8 + t];
            uint32_t aB2 = Ps[lrB0 * 68 + ks * 8 + t + 4];
            uint32_t aB3 = Ps[lrB1 * 68 + ks * 8 + t + 4];
#pragma unroll
            for (int nt = 0; nt < 8; nt++) {
                uint32_t b0 = Vs[(ks * 8 + t) * 72 + nt * 8 + g];
                uint32_t b1 = Vs[(ks * 8 + t + 4) * 72 + nt * 8 + g];
                mma_tf32(oA[nt][0], oA[nt][1], oA[nt][2], oA[nt][3],
                         aA0, aA1, aA2, aA3, b0, b1);
                mma_tf32(oB[nt][0], oB[nt][1], oB[nt][2], oB[nt][3],
                         aB0, aB1, aB2, aB3, b0, b1);
            }
        }
        __syncwarp();

        // ---- segment boundary: normalize + write, reset ----
        if (vt == 8 || vt == 11 || vt == 12) {
            float LA0 = lA0, LA1 = lA1, LB0 = lB0, LB1 = lB1;
            LA0 += __shfl_xor_sync(0xffffffffu, LA0, 1);
            LA0 += __shfl_xor_sync(0xffffffffu, LA0, 2);
            LA1 += __shfl_xor_sync(0xffffffffu, LA1, 1);
            LA1 += __shfl_xor_sync(0xffffffffu, LA1, 2);
            LB0 += __shfl_xor_sync(0xffffffffu, LB0, 1);
            LB0 += __shfl_xor_sync(0xffffffffu, LB0, 2);
            LB1 += __shfl_xor_sync(0xffffffffu, LB1, 1);
            LB1 += __shfl_xor_sync(0xffffffffu, LB1, 2);
            float iA0 = 1.f / (3.f * LA0), iA1 = 1.f / (3.f * LA1);
            float iB0 = 1.f / (3.f * LB0), iB1 = 1.f / (3.f * LB1);
            if (seg == 0) {
#pragma unroll
                for (int nt = 0; nt < 8; nt++) {
                    int col = nt * 8 + t * 2;
                    if (qiA0 < Tv) { cA0[col] = oA[nt][0] * iA0; cA0[col + 1] = oA[nt][1] * iA0; }
                    if (qiA1 < Tv) { cA1[col] = oA[nt][2] * iA1; cA1[col + 1] = oA[nt][3] * iA1; }
                    if (qiB0 < Tv) { cB0[col] = oB[nt][0] * iB0; cB0[col + 1] = oB[nt][1] * iB0; }
                    if (qiB1 < Tv) { cB1[col] = oB[nt][2] * iB1; cB1[col + 1] = oB[nt][3] * iB1; }
                }
            } else if (seg == 1) {
#pragma unroll
                for (int nt = 0; nt < 8; nt++) {
                    int col = nt * 8 + t * 2;
                    if (qiA0 < Tv) { cA0[col] += oA[nt][0] * iA0; cA0[col + 1] += oA[nt][1] * iA0; }
                    if (qiA1 < Tv) { cA1[col] += oA[nt][2] * iA1; cA1[col + 1] += oA[nt][3] * iA1; }
                    if (qiB0 < Tv) { cB0[col] += oB[nt][0] * iB0; cB0[col + 1] += oB[nt][1] * iB0; }
                    if (qiB1 < Tv) { cB1[col] += oB[nt][2] * iB1; cB1[col + 1] += oB[nt][3] * iB1; }
                }
            } else {
#pragma unroll
                for (int nt = 0; nt < 8; nt++) {
                    int col = nt * 8 + t * 2;
                    if (qiA0 < Tv) {
                        cA0[col] = __uint_as_float(f2tf(cA0[col] + oA[nt][0] * iA0));
                        cA0[col + 1] = __uint_as_float(f2tf(cA0[col + 1] + oA[nt][1] * iA0));
                    }
                    if (qiA1 < Tv) {
                        cA1[col] = __uint_as_float(f2tf(cA1[col] + oA[nt][2] * iA1));
                        cA1[col + 1] = __uint_as_float(f2tf(cA1[col + 1] + oA[nt][3] * iA1));
                    }
                    if (qiB0 < Tv) {
                        cB0[col] = __uint_as_float(f2tf(cB0[col] + oB[nt][0] * iB0));
                        cB0[col + 1] = __uint_as_float(f2tf(cB0[col + 1] + oB[nt][1] * iB0));
                    }
                    if (qiB1 < Tv) {
                        cB1[col] = __uint_as_float(f2tf(cB1[col] + oB[nt][2] * iB1));
                        cB1[col + 1] = __uint_as_float(f2tf(cB1[col + 1] + oB[nt][3] * iB1));
                    }
                }
            }
#pragma unroll
            for (int nt = 0; nt < 8; nt++)
#pragma unroll
                for (int r = 0; r < 4; r++) { oA[nt][r] = 0.f; oB[nt][r] = 0.f; }
            lA0 = lA1 = lB0 = lB1 = 0.f;
        }
    }
}

// ---------------- launch ------------------------------------------------------
extern "C" void kernel_launch(void* const* d_in, const int* in_sizes, int n_in,
                              void* d_out, int out_size) {
    const float* x    = (const float*)d_in[0];
    const float* wq   = (const float*)d_in[1];
    const float* wdkv = (const float*)d_in[2];
    const float* wuk1 = (const float*)d_in[3];
    const float* wuk2 = (const float*)d_in[4];
    const float* wuk4 = (const float*)d_in[5];
    const float* wuv1 = (const float*)d_in[6];
    const float* wuv2 = (const float*)d_in[7];
    const float* wuv4 = (const float*)d_in[8];
    const float* wout = (const float*)d_in[9];
    const float* bout = (const float*)d_in[10];
    const float* tbl1 = (const float*)d_in[11];
    const float* tbl2 = (const float*)d_in[12];
    const float* tbl4 = (const float*)d_in[13];

    float *q, *lat, *lp2, *lp4, *k, *v, *k2, *v2, *k4, *v4, *ctx, *wc, *xr, *bias;
    cudaGetSymbolAddress((void**)&q, g_q);
    cudaGetSymbolAddress((void**)&lat, g_lat);
    cudaGetSymbolAddress((void**)&lp2, g_lp2);
    cudaGetSymbolAddress((void**)&lp4, g_lp4);
    cudaGetSymbolAddress((void**)&k, g_k);
    cudaGetSymbolAddress((void**)&v, g_v);
    cudaGetSymbolAddress((void**)&k2, g_k2);
    cudaGetSymbolAddress((void**)&v2, g_v2);
    cudaGetSymbolAddress((void**)&k4, g_k4);
    cudaGetSymbolAddress((void**)&v4, g_v4);
    cudaGetSymbolAddress((void**)&ctx, g_ctx);
    cudaGetSymbolAddress((void**)&wc, g_wc);
    cudaGetSymbolAddress((void**)&xr, g_xr);
    cudaGetSymbolAddress((void**)&bias, g_bias);

    const int O_WQ = 0, O_WDKV = 589824, O_WUK1 = 786432, O_WUV1 = 983040;
    const int O_WUK2 = 1179648, O_WUV2 = 1376256, O_WUK4 = 1572864, O_WUV4 = 1769472;
    const int O_WOUT = 1966080;

    CvtArgs ca;
    ca.src[0] = wq;   ca.dst[0] = wc + O_WQ;   ca.n[0] = 589824;
    ca.src[1] = wdkv; ca.dst[1] = wc + O_WDKV; ca.n[1] = 196608;
    ca.src[2] = wuk1; ca.dst[2] = wc + O_WUK1; ca.n[2] = 196608;
    ca.src[3] = wuv1; ca.dst[3] = wc + O_WUV1; ca.n[3] = 196608;
    ca.src[4] = wuk2; ca.dst[4] = wc + O_WUK2; ca.n[4] = 196608;
    ca.src[5] = wuv2; ca.dst[5] = wc + O_WUV2; ca.n[5] = 196608;
    ca.src[6] = wuk4; ca.dst[6] = wc + O_WUK4; ca.n[6] = 196608;
    ca.src[7] = wuv4; ca.dst[7] = wc + O_WUV4; ca.n[7] = 196608;
    ca.src[8] = wout; ca.dst[8] = wc + O_WOUT; ca.n[8] = 589824;
    ca.src[9] = x;    ca.dst[9] = xr;          ca.n[9] = Bv * Tv * DMv;

    const int GEMM_SMEM = 17664 * 4;           // 70,656 B
    const int ATT_SMEM = ATT_SMEM_WORDS * 4;   // 106,496 B
    cudaFuncSetAttribute(gemm_tc, cudaFuncAttributeMaxDynamicSharedMemorySize,
                         GEMM_SMEM);
    cudaFuncSetAttribute(attn_fused, cudaFuncAttributeMaxDynamicSharedMemorySize,
                         ATT_SMEM);

    const int MQ = Bv * Tv;  // 9216

    cvtw_kernel<<<512, 256>>>(ca);

    // dense bias tables (independent of the GEMM chain)
    bias_pre<<<(NHv * 576 * 576 + 255) / 256, 256>>>(tbl1, bias, 1, 24, 576, 47);
    bias_pre<<<(NHv * 144 * 576 + 255) / 256, 256>>>(tbl2, bias + B2OFF, 2, 12, 144, 23);
    bias_pre<<<(NHv * 36 * 576 + 255) / 256, 256>>>(tbl4, bias + B4OFF, 4, 6, 36, 11);

    gemm_tc<<<dim3(6, 72), 256, GEMM_SMEM>>>(xr, wc + O_WQ, nullptr, nullptr,
                                             q, nullptr, MQ, DMv, DMv, 1);
    gemm_tc<<<dim3(2, 72), 256, GEMM_SMEM>>>(xr, wc + O_WDKV, nullptr, nullptr,
                                             lat, nullptr, MQ, LDv, DMv, 1);

    gemm_tc<<<dim3(6, 72, 2), 256, GEMM_SMEM>>>(lat, wc + O_WUK1, wc + O_WUV1,
                                                nullptr, k, v, MQ, DMv, LDv, 1);

    pool_kernel<<<(Bv * 144 * LDv + 255) / 256, 256>>>(lat, lp2, 2, 12, Bv * 144 * LDv);
    gemm_tc<<<dim3(6, 18, 2), 256, GEMM_SMEM>>>(lp2, wc + O_WUK2, wc + O_WUV2,
                                                nullptr, k2, v2, Bv * 144, DMv, LDv, 1);

    pool_kernel<<<(Bv * 36 * LDv + 255) / 256, 256>>>(lat, lp4, 4, 6, Bv * 36 * LDv);
    gemm_tc<<<dim3(6, 5, 2), 256, GEMM_SMEM>>>(lp4, wc + O_WUK4, wc + O_WUV4,
                                               nullptr, k4, v4, Bv * 36, DMv, LDv, 1);

    attn_fused<<<dim3(5, NHv, Bv), 128, ATT_SMEM>>>(q, k, v, k2, v2, k4, v4,
                                                    bias, ctx);

    gemm_tc<<<dim3(6, 72), 256, GEMM_SMEM>>>(ctx, wc + O_WOUT, nullptr, bout,
                                             (float*)d_out, nullptr, MQ, DMv, DMv, 0);
}

// round 7
// speedup vs baseline: 1.1881x; 1.1881x over previous
#include <cuda_runtime.h>
#include <cstdint>
#include <cstddef>

#define Bv 16
#define Tv 576
#define NHv 12
#define HDv 64
#define DMv 768
#define LDv 256

// ---------------- scratch (static device allocations; no cudaMalloc) ---------
__device__ float g_q[Bv * Tv * DMv];
__device__ float g_lat[Bv * Tv * LDv];
__device__ float g_lp2[Bv * 144 * LDv];
__device__ float g_lp4[Bv * 36 * LDv];
__device__ float g_k[Bv * Tv * DMv];
__device__ float g_v[Bv * Tv * DMv];
__device__ float g_k2[Bv * 144 * DMv];
__device__ float g_v2[Bv * 144 * DMv];
__device__ float g_k4[Bv * 36 * DMv];
__device__ float g_v4[Bv * 36 * DMv];
__device__ float g_ctx[Bv * Tv * DMv];
__device__ float g_wc[2555904];          // tf32-rounded, concatenated weights
__device__ float g_xr[Bv * Tv * DMv];    // tf32-rounded x

// ---------------- helpers -----------------------------------------------------
__device__ __forceinline__ uint32_t f2tf(float f) {
    uint32_t u;
    asm("cvt.rna.tf32.f32 %0, %1;" : "=r"(u) : "f"(f));
    return u;
}

__device__ __forceinline__ void mma_tf32(float& c0, float& c1, float& c2, float& c3,
                                         uint32_t a0, uint32_t a1, uint32_t a2, uint32_t a3,
                                         uint32_t b0, uint32_t b1) {
    asm volatile(
        "mma.sync.aligned.m16n8k8.row.col.f32.tf32.tf32.f32 "
        "{%0,%1,%2,%3}, {%4,%5,%6,%7}, {%8,%9}, {%0,%1,%2,%3};"
        : "+f"(c0), "+f"(c1), "+f"(c2), "+f"(c3)
        : "r"(a0), "r"(a1), "r"(a2), "r"(a3), "r"(b0), "r"(b1));
}

__device__ __forceinline__ void cpa16(uint32_t dst, const void* src) {
    asm volatile("cp.async.cg.shared.global [%0], [%1], 16;" :: "r"(dst), "l"(src));
}
__device__ __forceinline__ void cpa16z(uint32_t dst, const void* src, int pred) {
    asm volatile(
        "{\n\t.reg .pred p;\n\tsetp.ne.b32 p, %2, 0;\n\t"
        "@p cp.async.cg.shared.global [%0], [%1], 16;\n\t"
        "@!p cp.async.cg.shared.global [%0], [%1], 16, 0;\n\t}"
        :: "r"(dst), "l"(src), "r"(pred));
}
__device__ __forceinline__ void cp_commit() { asm volatile("cp.async.commit_group;"); }
__device__ __forceinline__ void cp_wait0() { asm volatile("cp.async.wait_group 0;"); }
__device__ __forceinline__ void cp_wait1() { asm volatile("cp.async.wait_group 1;"); }
__device__ __forceinline__ void cp_wait2() { asm volatile("cp.async.wait_group 2;"); }

// ---------------- tf32 pre-rounding with column-concatenation ------------------
struct CvtArgs {
    const float* src[10];
    float* dst[10];
    int n[10];
    int srcW[10];   // source row width
    int dstW[10];   // destination row width
    int colOff[10]; // destination column offset
};
__global__ void cvtw_kernel(CvtArgs a) {
    int gid = blockIdx.x * blockDim.x + threadIdx.x;
    int stride = gridDim.x * blockDim.x;
#pragma unroll
    for (int s = 0; s < 10; s++) {
        const float* sp = a.src[s];
        float* dp = a.dst[s];
        int n = a.n[s];
        int sw = a.srcW[s], dw = a.dstW[s], co = a.colOff[s];
        if (sw == dw && co == 0) {
            for (int i = gid; i < n; i += stride)
                dp[i] = __uint_as_float(f2tf(sp[i]));
        } else {
            for (int i = gid; i < n; i += stride) {
                int row = i / sw, col = i - row * sw;
                dp[row * dw + co + col] = __uint_as_float(f2tf(sp[i]));
            }
        }
    }
}

// ---------------- tf32 tensor-core GEMM, 4-stage cp.async, BK=16 ---------------
// C(/C2) = A(MxK) * Bw(KxN) (+bias). Columns [0,NS) -> C (row stride N1),
// [NS,N) -> C2 (row stride N2). 128x128 tile, 256 threads, warp tile 64x32.
// smem words: As 4 stages x 2560 at 0; Bs 4 stages x 2112 at 10240. 74,752 B.
__global__ __launch_bounds__(256, 2) void gemm_tc(
    const float* __restrict__ A, const float* __restrict__ Bw,
    const float* __restrict__ bias, float* __restrict__ C,
    float* __restrict__ C2, int M, int N, int K,
    int NS, int N1, int N2, int round_out) {
    extern __shared__ uint32_t sm[];
    const int bm = blockIdx.y * 128;
    const int bn = blockIdx.x * 128;
    const int tid = threadIdx.x;
    const int lane = tid & 31;
    const int warp = tid >> 5;
    const int wm = (warp & 1) * 64;
    const int wn = (warp >> 1) * 32;
    const int g = lane >> 2;
    const int t = lane & 3;
    const int nk = K >> 4;
    uint32_t sb = (uint32_t)__cvta_generic_to_shared(sm);

    auto issue = [&](int it) {
        int buf = it & 3;
        int k0 = it << 4;
#pragma unroll
        for (int u = 0; u < 2; u++) {
            int idx = u * 256 + tid;
            int r = idx >> 2;              // 0..127
            int c4 = (idx & 3) << 2;       // 0,4,8,12
            int pred = (bm + r) < M;
            cpa16z(sb + (buf * 2560 + r * 20 + c4) * 4,
                   A + (size_t)(bm + r) * K + k0 + c4, pred);
        }
#pragma unroll
        for (int u = 0; u < 2; u++) {
            int idx = u * 256 + tid;
            int kk = idx >> 5;             // 0..15
            int c4 = (idx & 31) << 2;      // 0..124
            cpa16(sb + (10240 + buf * 2112 + kk * 132 + c4) * 4,
                  Bw + (size_t)(k0 + kk) * N + bn + c4);
        }
        cp_commit();
    };

    float c[4][4][4];
#pragma unroll
    for (int mt = 0; mt < 4; mt++)
#pragma unroll
        for (int nt = 0; nt < 4; nt++)
#pragma unroll
            for (int r = 0; r < 4; r++) c[mt][nt][r] = 0.f;

    issue(0);
    issue(1);
    issue(2);

    for (int it = 0; it < nk; it++) {
        int rem = nk - 1 - it;  // stages issued beyond it
        if (rem >= 3) cp_wait2();
        else if (rem == 2) cp_wait1();
        else cp_wait0();
        __syncthreads();
        if (it + 3 < nk) issue(it + 3);
        const uint32_t* Ab = sm + (it & 3) * 2560;
        const uint32_t* Bb = sm + 10240 + (it & 3) * 2112;
#pragma unroll
        for (int ks = 0; ks < 2; ks++) {
            uint32_t af[4][4], bf[4][2];
#pragma unroll
            for (int mt = 0; mt < 4; mt++) {
                int r = wm + mt * 16 + g;
                af[mt][0] = Ab[r * 20 + ks * 8 + t];
                af[mt][1] = Ab[(r + 8) * 20 + ks * 8 + t];
                af[mt][2] = Ab[r * 20 + ks * 8 + t + 4];
                af[mt][3] = Ab[(r + 8) * 20 + ks * 8 + t + 4];
            }
#pragma unroll
            for (int nt = 0; nt < 4; nt++) {
                int col = wn + nt * 8 + g;
                bf[nt][0] = Bb[(ks * 8 + t) * 132 + col];
                bf[nt][1] = Bb[(ks * 8 + t + 4) * 132 + col];
            }
#pragma unroll
            for (int mt = 0; mt < 4; mt++)
#pragma unroll
                for (int nt = 0; nt < 4; nt++)
                    mma_tf32(c[mt][nt][0], c[mt][nt][1], c[mt][nt][2], c[mt][nt][3],
                             af[mt][0], af[mt][1], af[mt][2], af[mt][3],
                             bf[nt][0], bf[nt][1]);
        }
        __syncthreads();
    }

    // epilogue: route columns to C or C2
    float* Co;
    int col0, cstride;
    if (bn < NS) { Co = C; col0 = bn; cstride = N1; }
    else         { Co = C2; col0 = bn - NS; cstride = N2; }

#pragma unroll
    for (int mt = 0; mt < 4; mt++) {
#pragma unroll
        for (int nt = 0; nt < 4; nt++) {
            int row0 = bm + wm + mt * 16 + g;
            int col = col0 + wn + nt * 8 + t * 2;
            float b0 = bias ? bias[col] : 0.f;
            float b1 = bias ? bias[col + 1] : 0.f;
            float v0 = c[mt][nt][0] + b0, v1 = c[mt][nt][1] + b1;
            float v2 = c[mt][nt][2] + b0, v3 = c[mt][nt][3] + b1;
            if (round_out) {
                v0 = __uint_as_float(f2tf(v0)); v1 = __uint_as_float(f2tf(v1));
                v2 = __uint_as_float(f2tf(v2)); v3 = __uint_as_float(f2tf(v3));
            }
            if (row0 < M) *(float2*)(Co + (size_t)row0 * cstride + col) = make_float2(v0, v1);
            if (row0 + 8 < M) *(float2*)(Co + (size_t)(row0 + 8) * cstride + col) = make_float2(v2, v3);
        }
    }
}

// ---------------- exact sxs mean pooling (tf32-rounded output) ------------------
__global__ void pool_kernel(const float* __restrict__ lat, float* __restrict__ out,
                            int s, int g, int n) {
    int idx = blockIdx.x * blockDim.x + threadIdx.x;
    if (idx >= n) return;
    int c = idx & (LDv - 1);
    int rest = idx >> 8;
    int cell = rest % (g * g);
    int b = rest / (g * g);
    int gh = cell / g, gw = cell % g;
    float sum = 0.f;
    for (int i = 0; i < s; i++)
        for (int j = 0; j < s; j++)
            sum += lat[((size_t)(b * Tv) + (gh * s + i) * 24 + (gw * s + j)) * LDv + c];
    out[idx] = __uint_as_float(f2tf(sum / (float)(s * s)));
}

// ---------------- fused 3-scale tensor-core flash attention (R5 version) -------
#define ATT_SMEM_WORDS 26880

__global__ __launch_bounds__(256, 2) void attn_fused(
    const float* __restrict__ qbuf,
    const float* __restrict__ k1, const float* __restrict__ v1,
    const float* __restrict__ k2, const float* __restrict__ v2,
    const float* __restrict__ k4, const float* __restrict__ v4,
    const float* __restrict__ tbl1, const float* __restrict__ tbl2,
    const float* __restrict__ tbl4, float* __restrict__ ctx) {
    extern __shared__ uint32_t smu[];
    uint32_t* Ps = smu + 17920;
    float* khcs = (float*)(smu + 26624);
    float* kwcs = (float*)(smu + 26752);
    uint32_t sb = (uint32_t)__cvta_generic_to_shared(smu);

    const int b = blockIdx.z;
    const int h = blockIdx.y;
    const int q0 = blockIdx.x * 128;
    const int tid = threadIdx.x;
    const int lane = tid & 31;
    const int w = tid >> 5;
    const int g = lane >> 2;
    const int t = lane & 3;
    const int lr0 = w * 16 + g;
    const int lr1 = lr0 + 8;

    auto issue_kv = [&](int vt) {
        const float *kb, *vb;
        int Kt, kt;
        if (vt < 9) {
            kb = k1 + (size_t)b * 576 * DMv + h * HDv;
            vb = v1 + (size_t)b * 576 * DMv + h * HDv;
            Kt = 576; kt = vt;
        } else if (vt < 12) {
            kb = k2 + (size_t)b * 144 * DMv + h * HDv;
            vb = v2 + (size_t)b * 144 * DMv + h * HDv;
            Kt = 144; kt = vt - 9;
        } else {
            kb = k4 + (size_t)b * 36 * DMv + h * HDv;
            vb = v4 + (size_t)b * 36 * DMv + h * HDv;
            Kt = 36; kt = 0;
        }
        int buf = vt & 1;
#pragma unroll
        for (int u = 0; u < 4; u++) {
            int idx = u * 256 + tid;
            int r = idx >> 4;
            int c4 = (idx & 15) << 2;
            int kg = kt * 64 + r;
            int pred = kg < Kt;
            cpa16z(sb + (buf * 4352 + r * 68 + c4) * 4,
                   kb + (size_t)kg * DMv + c4, pred);
            cpa16z(sb + (8704 + buf * 4608 + r * 72 + c4) * 4,
                   vb + (size_t)kg * DMv + c4, pred);
        }
    };

    const float* qsrc = qbuf + ((size_t)(b * Tv)) * DMv + h * HDv;
#pragma unroll
    for (int u = 0; u < 8; u++) {
        int idx = u * 256 + tid;
        int r = idx >> 4;
        int c4 = (idx & 15) << 2;
        int row = q0 + r;
        if (row > Tv - 1) row = Tv - 1;
        *(float4*)((float*)&Ps[r * 68 + c4]) = *(const float4*)(qsrc + (size_t)row * DMv + c4);
    }
    issue_kv(0);
    cp_commit();
    __syncthreads();

    uint32_t qf[8][4];
#pragma unroll
    for (int kd = 0; kd < 8; kd++) {
        qf[kd][0] = Ps[lr0 * 68 + kd * 8 + t];
        qf[kd][1] = Ps[lr1 * 68 + kd * 8 + t];
        qf[kd][2] = Ps[lr0 * 68 + kd * 8 + t + 4];
        qf[kd][3] = Ps[lr1 * 68 + kd * 8 + t + 4];
    }

    float o[8][4];
#pragma unroll
    for (int nt = 0; nt < 8; nt++)
#pragma unroll
        for (int r = 0; r < 4; r++) o[nt][r] = 0.f;
    float l0 = 0.f, l1 = 0.f;

    const float scl = 0.125f;
    const int qi0 = q0 + lr0;
    const int qi1 = q0 + lr1;
    const int qc0 = qi0 < Tv ? qi0 : Tv - 1;
    const int qc1 = qi1 < Tv ? qi1 : Tv - 1;
    const float qh0 = (float)(qc0 / 24), qw0 = (float)(qc0 % 24);
    const float qh1 = (float)(qc1 / 24), qw1 = (float)(qc1 % 24);
    float* c0p = ctx + ((size_t)(b * Tv + qc0)) * DMv + h * HDv;
    float* c1p = ctx + ((size_t)(b * Tv + qc1)) * DMv + h * HDv;

    for (int vt = 0; vt < 13; vt++) {
        int seg, Kt, kt, gw_, s_, tw_;
        const float* tb;
        if (vt < 9)       { seg = 0; Kt = 576; kt = vt;      gw_ = 24; s_ = 1; tw_ = 47; tb = tbl1 + h * (47 * 47); }
        else if (vt < 12) { seg = 1; Kt = 144; kt = vt - 9;  gw_ = 12; s_ = 2; tw_ = 23; tb = tbl2 + h * (47 * 23); }
        else              { seg = 2; Kt = 36;  kt = 0;       gw_ = 6;  s_ = 4; tw_ = 11; tb = tbl4 + h * (47 * 11); }
        const float hctr = 0.5f * (float)(s_ - 1);
        const int buf = vt & 1;

        cp_wait0();
        if (tid < 64) {
            int kg = kt * 64 + tid;
            if (kg < Kt) {
                khcs[buf * 64 + tid] = (float)((kg / gw_) * s_) + hctr;
                kwcs[buf * 64 + tid] = (float)((kg % gw_) * s_) + hctr;
            }
        }
        __syncthreads();
        if (vt + 1 < 13) { issue_kv(vt + 1); cp_commit(); }

        const uint32_t* Ks = smu + buf * 4352;
        const uint32_t* Vs = smu + 8704 + buf * 4608;

        float sf[8][4];
#pragma unroll
        for (int nt = 0; nt < 8; nt++)
#pragma unroll
            for (int r = 0; r < 4; r++) sf[nt][r] = 0.f;
#pragma unroll
        for (int kd = 0; kd < 8; kd++) {
#pragma unroll
            for (int nt = 0; nt < 8; nt++) {
                uint32_t b0 = Ks[(nt * 8 + g) * 68 + kd * 8 + t];
                uint32_t b1 = Ks[(nt * 8 + g) * 68 + kd * 8 + t + 4];
                mma_tf32(sf[nt][0], sf[nt][1], sf[nt][2], sf[nt][3],
                         qf[kd][0], qf[kd][1], qf[kd][2], qf[kd][3], b0, b1);
            }
        }

#pragma unroll
        for (int nt = 0; nt < 8; nt++) {
#pragma unroll
            for (int cc = 0; cc < 2; cc++) {
                int lc = nt * 8 + t * 2 + cc;
                int kg = kt * 64 + lc;
                float p0 = 0.f, p1 = 0.f;
                if (kg < Kt) {
                    float khc = khcs[buf * 64 + lc], kwc = kwcs[buf * 64 + lc];
                    int rh0 = (int)(qh0 - khc) + 23;
                    int rw0 = (int)(qw0 - kwc) + (gw_ - 1);
                    int rh1 = (int)(qh1 - khc) + 23;
                    int rw1 = (int)(qw1 - kwc) + (gw_ - 1);
                    p0 = __expf(sf[nt][cc] * scl + __ldg(&tb[rh0 * tw_ + rw0]));
                    p1 = __expf(sf[nt][cc + 2] * scl + __ldg(&tb[rh1 * tw_ + rw1]));
                }
                l0 += p0;
                l1 += p1;
                Ps[lr0 * 68 + lc] = f2tf(p0);
                Ps[lr1 * 68 + lc] = f2tf(p1);
            }
        }
        __syncwarp();

#pragma unroll
        for (int ks = 0; ks < 8; ks++) {
            uint32_t a0 = Ps[lr0 * 68 + ks * 8 + t];
            uint32_t a1 = Ps[lr1 * 68 + ks * 8 + t];
            uint32_t a2 = Ps[lr0 * 68 + ks * 8 + t + 4];
            uint32_t a3 = Ps[lr1 * 68 + ks * 8 + t + 4];
#pragma unroll
            for (int nt = 0; nt < 8; nt++) {
                uint32_t b0 = Vs[(ks * 8 + t) * 72 + nt * 8 + g];
                uint32_t b1 = Vs[(ks * 8 + t + 4) * 72 + nt * 8 + g];
                mma_tf32(o[nt][0], o[nt][1], o[nt][2], o[nt][3],
                         a0, a1, a2, a3, b0, b1);
            }
        }
        __syncwarp();

        if (vt == 8 || vt == 11 || vt == 12) {
            float L0 = l0, L1 = l1;
            L0 += __shfl_xor_sync(0xffffffffu, L0, 1);
            L0 += __shfl_xor_sync(0xffffffffu, L0, 2);
            L1 += __shfl_xor_sync(0xffffffffu, L1, 1);
            L1 += __shfl_xor_sync(0xffffffffu, L1, 2);
            float inv0 = 1.f / (3.f * L0);
            float inv1 = 1.f / (3.f * L1);
            if (seg == 0) {
#pragma unroll
                for (int nt = 0; nt < 8; nt++) {
                    int col = nt * 8 + t * 2;
                    if (qi0 < Tv) {
                        c0p[col] = o[nt][0] * inv0;
                        c0p[col + 1] = o[nt][1] * inv0;
                    }
                    if (qi1 < Tv) {
                        c1p[col] = o[nt][2] * inv1;
                        c1p[col + 1] = o[nt][3] * inv1;
                    }
                }
            } else if (seg == 1) {
#pragma unroll
                for (int nt = 0; nt < 8; nt++) {
                    int col = nt * 8 + t * 2;
                    if (qi0 < Tv) {
                        c0p[col] += o[nt][0] * inv0;
                        c0p[col + 1] += o[nt][1] * inv0;
                    }
                    if (qi1 < Tv) {
                        c1p[col] += o[nt][2] * inv1;
                        c1p[col + 1] += o[nt][3] * inv1;
                    }
                }
            } else {
#pragma unroll
                for (int nt = 0; nt < 8; nt++) {
                    int col = nt * 8 + t * 2;
                    if (qi0 < Tv) {
                        c0p[col] = __uint_as_float(f2tf(c0p[col] + o[nt][0] * inv0));
                        c0p[col + 1] = __uint_as_float(f2tf(c0p[col + 1] + o[nt][1] * inv0));
                    }
                    if (qi1 < Tv) {
                        c1p[col] = __uint_as_float(f2tf(c1p[col] + o[nt][2] * inv1));
                        c1p[col + 1] = __uint_as_float(f2tf(c1p[col + 1] + o[nt][3] * inv1));
                    }
                }
            }
#pragma unroll
            for (int nt = 0; nt < 8; nt++)
#pragma unroll
                for (int r = 0; r < 4; r++) o[nt][r] = 0.f;
            l0 = 0.f;
            l1 = 0.f;
        }
    }
}

// ---------------- launch ------------------------------------------------------
extern "C" void kernel_launch(void* const* d_in, const int* in_sizes, int n_in,
                              void* d_out, int out_size) {
    const float* x    = (const float*)d_in[0];
    const float* wq   = (const float*)d_in[1];
    const float* wdkv = (const float*)d_in[2];
    const float* wuk1 = (const float*)d_in[3];
    const float* wuk2 = (const float*)d_in[4];
    const float* wuk4 = (const float*)d_in[5];
    const float* wuv1 = (const float*)d_in[6];
    const float* wuv2 = (const float*)d_in[7];
    const float* wuv4 = (const float*)d_in[8];
    const float* wout = (const float*)d_in[9];
    const float* bout = (const float*)d_in[10];
    const float* tbl1 = (const float*)d_in[11];
    const float* tbl2 = (const float*)d_in[12];
    const float* tbl4 = (const float*)d_in[13];

    float *q, *lat, *lp2, *lp4, *k, *v, *k2, *v2, *k4, *v4, *ctx, *wc, *xr;
    cudaGetSymbolAddress((void**)&q, g_q);
    cudaGetSymbolAddress((void**)&lat, g_lat);
    cudaGetSymbolAddress((void**)&lp2, g_lp2);
    cudaGetSymbolAddress((void**)&lp4, g_lp4);
    cudaGetSymbolAddress((void**)&k, g_k);
    cudaGetSymbolAddress((void**)&v, g_v);
    cudaGetSymbolAddress((void**)&k2, g_k2);
    cudaGetSymbolAddress((void**)&v2, g_v2);
    cudaGetSymbolAddress((void**)&k4, g_k4);
    cudaGetSymbolAddress((void**)&v4, g_v4);
    cudaGetSymbolAddress((void**)&ctx, g_ctx);
    cudaGetSymbolAddress((void**)&wc, g_wc);
    cudaGetSymbolAddress((void**)&xr, g_xr);

    // concatenated weight layout in g_wc
    const int O_WQL = 0;        // [768 x 1024]: wq | wdkv
    const int O_KV1 = 786432;   // [256 x 1536]: wuk1 | wuv1
    const int O_KV2 = 1179648;  // [256 x 1536]: wuk2 | wuv2
    const int O_KV4 = 1572864;  // [256 x 1536]: wuk4 | wuv4
    const int O_WOUT = 1966080; // [768 x 768]

    CvtArgs ca;
    ca.src[0] = wq;   ca.dst[0] = wc + O_WQL;  ca.n[0] = 589824; ca.srcW[0] = 768; ca.dstW[0] = 1024; ca.colOff[0] = 0;
    ca.src[1] = wdkv; ca.dst[1] = wc + O_WQL;  ca.n[1] = 196608; ca.srcW[1] = 256; ca.dstW[1] = 1024; ca.colOff[1] = 768;
    ca.src[2] = wuk1; ca.dst[2] = wc + O_KV1;  ca.n[2] = 196608; ca.srcW[2] = 768; ca.dstW[2] = 1536; ca.colOff[2] = 0;
    ca.src[3] = wuv1; ca.dst[3] = wc + O_KV1;  ca.n[3] = 196608; ca.srcW[3] = 768; ca.dstW[3] = 1536; ca.colOff[3] = 768;
    ca.src[4] = wuk2; ca.dst[4] = wc + O_KV2;  ca.n[4] = 196608; ca.srcW[4] = 768; ca.dstW[4] = 1536; ca.colOff[4] = 0;
    ca.src[5] = wuv2; ca.dst[5] = wc + O_KV2;  ca.n[5] = 196608; ca.srcW[5] = 768; ca.dstW[5] = 1536; ca.colOff[5] = 768;
    ca.src[6] = wuk4; ca.dst[6] = wc + O_KV4;  ca.n[6] = 196608; ca.srcW[6] = 768; ca.dstW[6] = 1536; ca.colOff[6] = 0;
    ca.src[7] = wuv4; ca.dst[7] = wc + O_KV4;  ca.n[7] = 196608; ca.srcW[7] = 768; ca.dstW[7] = 1536; ca.colOff[7] = 768;
    ca.src[8] = wout; ca.dst[8] = wc + O_WOUT; ca.n[8] = 589824; ca.srcW[8] = 768; ca.dstW[8] = 768;  ca.colOff[8] = 0;
    ca.src[9] = x;    ca.dst[9] = xr;          ca.n[9] = Bv * Tv * DMv; ca.srcW[9] = 768; ca.dstW[9] = 768; ca.colOff[9] = 0;

    const int GEMM_SMEM = 18688 * 4;           // 74,752 B
    const int ATT_SMEM = ATT_SMEM_WORDS * 4;   // 107,520 B
    cudaFuncSetAttribute(gemm_tc, cudaFuncAttributeMaxDynamicSharedMemorySize,
                         GEMM_SMEM);
    cudaFuncSetAttribute(attn_fused, cudaFuncAttributeMaxDynamicSharedMemorySize,
                         ATT_SMEM);

    const int MQ = Bv * Tv;  // 9216

    cvtw_kernel<<<512, 256>>>(ca);

    // q + lat in one launch: N=1024, split at 768
    gemm_tc<<<dim3(8, 72), 256, GEMM_SMEM>>>(xr, wc + O_WQL, nullptr, q, lat,
                                             MQ, 1024, DMv, 768, DMv, LDv, 1);

    pool_kernel<<<(Bv * 144 * LDv + 255) / 256, 256>>>(lat, lp2, 2, 12, Bv * 144 * LDv);
    pool_kernel<<<(Bv * 36 * LDv + 255) / 256, 256>>>(lat, lp4, 4, 6, Bv * 36 * LDv);

    // k|v fused per scale: N=1536, split at 768
    gemm_tc<<<dim3(12, 72), 256, GEMM_SMEM>>>(lat, wc + O_KV1, nullptr, k, v,
                                              MQ, 1536, LDv, 768, DMv, DMv, 1);
    gemm_tc<<<dim3(12, 18), 256, GEMM_SMEM>>>(lp2, wc + O_KV2, nullptr, k2, v2,
                                              Bv * 144, 1536, LDv, 768, DMv, DMv, 1);
    gemm_tc<<<dim3(12, 5), 256, GEMM_SMEM>>>(lp4, wc + O_KV4, nullptr, k4, v4,
                                             Bv * 36, 1536, LDv, 768, DMv, DMv, 1);

    attn_fused<<<dim3(5, NHv, Bv), 256, ATT_SMEM>>>(q, k, v, k2, v2, k4, v4,
                                                    tbl1, tbl2, tbl4, ctx);

    gemm_tc<<<dim3(6, 72), 256, GEMM_SMEM>>>(ctx, wc + O_WOUT, bout, (float*)d_out,
                                             nullptr, MQ, DMv, DMv, DMv, DMv, DMv, 0);
}

// round 8
// speedup vs baseline: 1.2759x; 1.0739x over previous
#include <cuda_runtime.h>
#include <cstdint>
#include <cstddef>

#define Bv 16
#define Tv 576
#define NHv 12
#define HDv 64
#define DMv 768
#define LDv 256

// ---------------- scratch (static device allocations; no cudaMalloc) ---------
__device__ float g_q[Bv * Tv * DMv];
__device__ float g_lat[Bv * Tv * LDv];
__device__ float g_lp2[Bv * 144 * LDv];
__device__ float g_lp4[Bv * 36 * LDv];
__device__ float g_k[Bv * Tv * DMv];
__device__ float g_v[Bv * Tv * DMv];
__device__ float g_k2[Bv * 144 * DMv];
__device__ float g_v2[Bv * 144 * DMv];
__device__ float g_k4[Bv * 36 * DMv];
__device__ float g_v4[Bv * 36 * DMv];
__device__ float g_ctx[Bv * Tv * DMv];
__device__ float g_wc[2555904];          // tf32-rounded weights
__device__ float g_xr[Bv * Tv * DMv];    // tf32-rounded x

// ---------------- helpers -----------------------------------------------------
__device__ __forceinline__ uint32_t f2tf(float f) {
    uint32_t u;
    asm("cvt.rna.tf32.f32 %0, %1;" : "=r"(u) : "f"(f));
    return u;
}

__device__ __forceinline__ void mma_tf32(float& c0, float& c1, float& c2, float& c3,
                                         uint32_t a0, uint32_t a1, uint32_t a2, uint32_t a3,
                                         uint32_t b0, uint32_t b1) {
    asm volatile(
        "mma.sync.aligned.m16n8k8.row.col.f32.tf32.tf32.f32 "
        "{%0,%1,%2,%3}, {%4,%5,%6,%7}, {%8,%9}, {%0,%1,%2,%3};"
        : "+f"(c0), "+f"(c1), "+f"(c2), "+f"(c3)
        : "r"(a0), "r"(a1), "r"(a2), "r"(a3), "r"(b0), "r"(b1));
}

__device__ __forceinline__ void cpa16(uint32_t dst, const void* src) {
    asm volatile("cp.async.cg.shared.global [%0], [%1], 16;" :: "r"(dst), "l"(src));
}
__device__ __forceinline__ void cpa16z(uint32_t dst, const void* src, int pred) {
    asm volatile(
        "{\n\t.reg .pred p;\n\tsetp.ne.b32 p, %2, 0;\n\t"
        "@p cp.async.cg.shared.global [%0], [%1], 16;\n\t"
        "@!p cp.async.cg.shared.global [%0], [%1], 16, 0;\n\t}"
        :: "r"(dst), "l"(src), "r"(pred));
}
__device__ __forceinline__ void cp_commit() { asm volatile("cp.async.commit_group;"); }
__device__ __forceinline__ void cp_wait0() { asm volatile("cp.async.wait_group 0;"); }
__device__ __forceinline__ void cp_wait1() { asm volatile("cp.async.wait_group 1;"); }

// ---------------- tf32 pre-rounding (weights + x) ------------------------------
struct CvtArgs {
    const float* src[10];
    float* dst[10];
    int n[10];
};
__global__ void cvtw_kernel(CvtArgs a) {
    int gid = blockIdx.x * blockDim.x + threadIdx.x;
    int stride = gridDim.x * blockDim.x;
#pragma unroll
    for (int s = 0; s < 10; s++) {
        const float* sp = a.src[s];
        float* dp = a.dst[s];
        int n = a.n[s];
        for (int i = gid; i < n; i += stride)
            dp[i] = __uint_as_float(f2tf(sp[i]));
    }
}

// ---------------- tf32 tensor-core GEMM, 3-stage cp.async, BK=32 ---------------
// C = A(MxK) * Bw(KxN) (+bias). A and B pre-rounded tf32-in-fp32 in gmem.
// 128x128 tile, 256 threads (8 warps, warp tile 64x32), 3-stage ring.
// smem words: As 3 x 4608 at 0 (stride 36); Bs 3 x 4352 at 13824 (stride 136,
// 136 mod 32 = 8 -> B-fragment lanes hit banks 8t+g: conflict-free).
// Total 26880 words = 107,520 B (2 CTAs/SM).
__global__ __launch_bounds__(256, 2) void gemm_tc(
    const float* __restrict__ A, const float* __restrict__ Bw,
    const float* __restrict__ B2, const float* __restrict__ bias,
    float* __restrict__ C, float* __restrict__ C2,
    int M, int N, int K, int round_out) {
    if (blockIdx.z == 1) { Bw = B2; C = C2; }

    extern __shared__ uint32_t sm[];
    const int bm = blockIdx.y * 128;
    const int bn = blockIdx.x * 128;
    const int tid = threadIdx.x;
    const int lane = tid & 31;
    const int warp = tid >> 5;
    const int wm = (warp & 1) * 64;
    const int wn = (warp >> 1) * 32;
    const int g = lane >> 2;
    const int t = lane & 3;
    const int nk = K >> 5;
    uint32_t sb = (uint32_t)__cvta_generic_to_shared(sm);

    auto issue = [&](int it) {
        int buf = it % 3;
        int k0 = it << 5;
#pragma unroll
        for (int u = 0; u < 4; u++) {
            int idx = u * 256 + tid;
            int r = idx >> 3;              // A row 0..127
            int c4 = (idx & 7) << 2;       // A col 0..28
            int pred = (bm + r) < M;
            cpa16z(sb + (buf * 4608 + r * 36 + c4) * 4,
                   A + (size_t)(bm + r) * K + k0 + c4, pred);
        }
#pragma unroll
        for (int u = 0; u < 4; u++) {
            int idx = u * 256 + tid;
            int kk = idx >> 5;             // B row 0..31
            int c4 = (idx & 31) << 2;      // B col 0..124
            cpa16(sb + (13824 + buf * 4352 + kk * 136 + c4) * 4,
                  Bw + (size_t)(k0 + kk) * N + bn + c4);
        }
        cp_commit();
    };

    float c[4][4][4];
#pragma unroll
    for (int mt = 0; mt < 4; mt++)
#pragma unroll
        for (int nt = 0; nt < 4; nt++)
#pragma unroll
            for (int r = 0; r < 4; r++) c[mt][nt][r] = 0.f;

    issue(0);
    issue(1);

    for (int it = 0; it < nk; it++) {
        if (it + 1 < nk) cp_wait1(); else cp_wait0();
        __syncthreads();
        if (it + 2 < nk) issue(it + 2);
        const uint32_t* Ab = sm + (it % 3) * 4608;
        const uint32_t* Bb = sm + 13824 + (it % 3) * 4352;
#pragma unroll
        for (int ks = 0; ks < 4; ks++) {
            uint32_t af[4][4], bf[4][2];
#pragma unroll
            for (int mt = 0; mt < 4; mt++) {
                int r = wm + mt * 16 + g;
                af[mt][0] = Ab[r * 36 + ks * 8 + t];
                af[mt][1] = Ab[(r + 8) * 36 + ks * 8 + t];
                af[mt][2] = Ab[r * 36 + ks * 8 + t + 4];
                af[mt][3] = Ab[(r + 8) * 36 + ks * 8 + t + 4];
            }
#pragma unroll
            for (int nt = 0; nt < 4; nt++) {
                int col = wn + nt * 8 + g;
                bf[nt][0] = Bb[(ks * 8 + t) * 136 + col];
                bf[nt][1] = Bb[(ks * 8 + t + 4) * 136 + col];
            }
#pragma unroll
            for (int mt = 0; mt < 4; mt++)
#pragma unroll
                for (int nt = 0; nt < 4; nt++)
                    mma_tf32(c[mt][nt][0], c[mt][nt][1], c[mt][nt][2], c[mt][nt][3],
                             af[mt][0], af[mt][1], af[mt][2], af[mt][3],
                             bf[nt][0], bf[nt][1]);
        }
        __syncthreads();
    }

#pragma unroll
    for (int mt = 0; mt < 4; mt++) {
#pragma unroll
        for (int nt = 0; nt < 4; nt++) {
            int row0 = bm + wm + mt * 16 + g;
            int col = bn + wn + nt * 8 + t * 2;
            float b0 = bias ? bias[col] : 0.f;
            float b1 = bias ? bias[col + 1] : 0.f;
            float v0 = c[mt][nt][0] + b0, v1 = c[mt][nt][1] + b1;
            float v2 = c[mt][nt][2] + b0, v3 = c[mt][nt][3] + b1;
            if (round_out) {
                v0 = __uint_as_float(f2tf(v0)); v1 = __uint_as_float(f2tf(v1));
                v2 = __uint_as_float(f2tf(v2)); v3 = __uint_as_float(f2tf(v3));
            }
            if (row0 < M) *(float2*)(C + (size_t)row0 * N + col) = make_float2(v0, v1);
            if (row0 + 8 < M) *(float2*)(C + (size_t)(row0 + 8) * N + col) = make_float2(v2, v3);
        }
    }
}

// ---------------- exact sxs mean pooling (tf32-rounded output) ------------------
__global__ void pool_kernel(const float* __restrict__ lat, float* __restrict__ out,
                            int s, int g, int n) {
    int idx = blockIdx.x * blockDim.x + threadIdx.x;
    if (idx >= n) return;
    int c = idx & (LDv - 1);
    int rest = idx >> 8;
    int cell = rest % (g * g);
    int b = rest / (g * g);
    int gh = cell / g, gw = cell % g;
    float sum = 0.f;
    for (int i = 0; i < s; i++)
        for (int j = 0; j < s; j++)
            sum += lat[((size_t)(b * Tv) + (gh * s + i) * 24 + (gw * s + j)) * LDv + c];
    out[idx] = __uint_as_float(f2tf(sum / (float)(s * s)));
}

// ---------------- fused 3-scale tensor-core flash attention (R5 version) -------
#define ATT_SMEM_WORDS 26880

__global__ __launch_bounds__(256, 2) void attn_fused(
    const float* __restrict__ qbuf,
    const float* __restrict__ k1, const float* __restrict__ v1,
    const float* __restrict__ k2, const float* __restrict__ v2,
    const float* __restrict__ k4, const float* __restrict__ v4,
    const float* __restrict__ tbl1, const float* __restrict__ tbl2,
    const float* __restrict__ tbl4, float* __restrict__ ctx) {
    extern __shared__ uint32_t smu[];
    uint32_t* Ps = smu + 17920;
    float* khcs = (float*)(smu + 26624);
    float* kwcs = (float*)(smu + 26752);
    uint32_t sb = (uint32_t)__cvta_generic_to_shared(smu);

    const int b = blockIdx.z;
    const int h = blockIdx.y;
    const int q0 = blockIdx.x * 128;
    const int tid = threadIdx.x;
    const int lane = tid & 31;
    const int w = tid >> 5;
    const int g = lane >> 2;
    const int t = lane & 3;
    const int lr0 = w * 16 + g;
    const int lr1 = lr0 + 8;

    auto issue_kv = [&](int vt) {
        const float *kb, *vb;
        int Kt, kt;
        if (vt < 9) {
            kb = k1 + (size_t)b * 576 * DMv + h * HDv;
            vb = v1 + (size_t)b * 576 * DMv + h * HDv;
            Kt = 576; kt = vt;
        } else if (vt < 12) {
            kb = k2 + (size_t)b * 144 * DMv + h * HDv;
            vb = v2 + (size_t)b * 144 * DMv + h * HDv;
            Kt = 144; kt = vt - 9;
        } else {
            kb = k4 + (size_t)b * 36 * DMv + h * HDv;
            vb = v4 + (size_t)b * 36 * DMv + h * HDv;
            Kt = 36; kt = 0;
        }
        int buf = vt & 1;
#pragma unroll
        for (int u = 0; u < 4; u++) {
            int idx = u * 256 + tid;
            int r = idx >> 4;
            int c4 = (idx & 15) << 2;
            int kg = kt * 64 + r;
            int pred = kg < Kt;
            cpa16z(sb + (buf * 4352 + r * 68 + c4) * 4,
                   kb + (size_t)kg * DMv + c4, pred);
            cpa16z(sb + (8704 + buf * 4608 + r * 72 + c4) * 4,
                   vb + (size_t)kg * DMv + c4, pred);
        }
    };

    const float* qsrc = qbuf + ((size_t)(b * Tv)) * DMv + h * HDv;
#pragma unroll
    for (int u = 0; u < 8; u++) {
        int idx = u * 256 + tid;
        int r = idx >> 4;
        int c4 = (idx & 15) << 2;
        int row = q0 + r;
        if (row > Tv - 1) row = Tv - 1;
        *(float4*)((float*)&Ps[r * 68 + c4]) = *(const float4*)(qsrc + (size_t)row * DMv + c4);
    }
    issue_kv(0);
    cp_commit();
    __syncthreads();

    uint32_t qf[8][4];
#pragma unroll
    for (int kd = 0; kd < 8; kd++) {
        qf[kd][0] = Ps[lr0 * 68 + kd * 8 + t];
        qf[kd][1] = Ps[lr1 * 68 + kd * 8 + t];
        qf[kd][2] = Ps[lr0 * 68 + kd * 8 + t + 4];
        qf[kd][3] = Ps[lr1 * 68 + kd * 8 + t + 4];
    }

    float o[8][4];
#pragma unroll
    for (int nt = 0; nt < 8; nt++)
#pragma unroll
        for (int r = 0; r < 4; r++) o[nt][r] = 0.f;
    float l0 = 0.f, l1 = 0.f;

    const float scl = 0.125f;
    const int qi0 = q0 + lr0;
    const int qi1 = q0 + lr1;
    const int qc0 = qi0 < Tv ? qi0 : Tv - 1;
    const int qc1 = qi1 < Tv ? qi1 : Tv - 1;
    const float qh0 = (float)(qc0 / 24), qw0 = (float)(qc0 % 24);
    const float qh1 = (float)(qc1 / 24), qw1 = (float)(qc1 % 24);
    float* c0p = ctx + ((size_t)(b * Tv + qc0)) * DMv + h * HDv;
    float* c1p = ctx + ((size_t)(b * Tv + qc1)) * DMv + h * HDv;

    for (int vt = 0; vt < 13; vt++) {
        int seg, Kt, kt, gw_, s_, tw_;
        const float* tb;
        if (vt < 9)       { seg = 0; Kt = 576; kt = vt;      gw_ = 24; s_ = 1; tw_ = 47; tb = tbl1 + h * (47 * 47); }
        else if (vt < 12) { seg = 1; Kt = 144; kt = vt - 9;  gw_ = 12; s_ = 2; tw_ = 23; tb = tbl2 + h * (47 * 23); }
        else              { seg = 2; Kt = 36;  kt = 0;       gw_ = 6;  s_ = 4; tw_ = 11; tb = tbl4 + h * (47 * 11); }
        const float hctr = 0.5f * (float)(s_ - 1);
        const int buf = vt & 1;

        cp_wait0();
        if (tid < 64) {
            int kg = kt * 64 + tid;
            if (kg < Kt) {
                khcs[buf * 64 + tid] = (float)((kg / gw_) * s_) + hctr;
                kwcs[buf * 64 + tid] = (float)((kg % gw_) * s_) + hctr;
            }
        }
        __syncthreads();
        if (vt + 1 < 13) { issue_kv(vt + 1); cp_commit(); }

        const uint32_t* Ks = smu + buf * 4352;
        const uint32_t* Vs = smu + 8704 + buf * 4608;

        float sf[8][4];
#pragma unroll
        for (int nt = 0; nt < 8; nt++)
#pragma unroll
            for (int r = 0; r < 4; r++) sf[nt][r] = 0.f;
#pragma unroll
        for (int kd = 0; kd < 8; kd++) {
#pragma unroll
            for (int nt = 0; nt < 8; nt++) {
                uint32_t b0 = Ks[(nt * 8 + g) * 68 + kd * 8 + t];
                uint32_t b1 = Ks[(nt * 8 + g) * 68 + kd * 8 + t + 4];
                mma_tf32(sf[nt][0], sf[nt][1], sf[nt][2], sf[nt][3],
                         qf[kd][0], qf[kd][1], qf[kd][2], qf[kd][3], b0, b1);
            }
        }

#pragma unroll
        for (int nt = 0; nt < 8; nt++) {
#pragma unroll
            for (int cc = 0; cc < 2; cc++) {
                int lc = nt * 8 + t * 2 + cc;
                int kg = kt * 64 + lc;
                float p0 = 0.f, p1 = 0.f;
                if (kg < Kt) {
                    float khc = khcs[buf * 64 + lc], kwc = kwcs[buf * 64 + lc];
                    int rh0 = (int)(qh0 - khc) + 23;
                    int rw0 = (int)(qw0 - kwc) + (gw_ - 1);
                    int rh1 = (int)(qh1 - khc) + 23;
                    int rw1 = (int)(qw1 - kwc) + (gw_ - 1);
                    p0 = __expf(sf[nt][cc] * scl + __ldg(&tb[rh0 * tw_ + rw0]));
                    p1 = __expf(sf[nt][cc + 2] * scl + __ldg(&tb[rh1 * tw_ + rw1]));
                }
                l0 += p0;
                l1 += p1;
                Ps[lr0 * 68 + lc] = f2tf(p0);
                Ps[lr1 * 68 + lc] = f2tf(p1);
            }
        }
        __syncwarp();

#pragma unroll
        for (int ks = 0; ks < 8; ks++) {
            uint32_t a0 = Ps[lr0 * 68 + ks * 8 + t];
            uint32_t a1 = Ps[lr1 * 68 + ks * 8 + t];
            uint32_t a2 = Ps[lr0 * 68 + ks * 8 + t + 4];
            uint32_t a3 = Ps[lr1 * 68 + ks * 8 + t + 4];
#pragma unroll
            for (int nt = 0; nt < 8; nt++) {
                uint32_t b0 = Vs[(ks * 8 + t) * 72 + nt * 8 + g];
                uint32_t b1 = Vs[(ks * 8 + t + 4) * 72 + nt * 8 + g];
                mma_tf32(o[nt][0], o[nt][1], o[nt][2], o[nt][3],
                         a0, a1, a2, a3, b0, b1);
            }
        }
        __syncwarp();

        if (vt == 8 || vt == 11 || vt == 12) {
            float L0 = l0, L1 = l1;
            L0 += __shfl_xor_sync(0xffffffffu, L0, 1);
            L0 += __shfl_xor_sync(0xffffffffu, L0, 2);
            L1 += __shfl_xor_sync(0xffffffffu, L1, 1);
            L1 += __shfl_xor_sync(0xffffffffu, L1, 2);
            float inv0 = 1.f / (3.f * L0);
            float inv1 = 1.f / (3.f * L1);
            if (seg == 0) {
#pragma unroll
                for (int nt = 0; nt < 8; nt++) {
                    int col = nt * 8 + t * 2;
                    if (qi0 < Tv) {
                        c0p[col] = o[nt][0] * inv0;
                        c0p[col + 1] = o[nt][1] * inv0;
                    }
                    if (qi1 < Tv) {
                        c1p[col] = o[nt][2] * inv1;
                        c1p[col + 1] = o[nt][3] * inv1;
                    }
                }
            } else if (seg == 1) {
#pragma unroll
                for (int nt = 0; nt < 8; nt++) {
                    int col = nt * 8 + t * 2;
                    if (qi0 < Tv) {
                        c0p[col] += o[nt][0] * inv0;
                        c0p[col + 1] += o[nt][1] * inv0;
                    }
                    if (qi1 < Tv) {
                        c1p[col] += o[nt][2] * inv1;
                        c1p[col + 1] += o[nt][3] * inv1;
                    }
                }
            } else {
#pragma unroll
                for (int nt = 0; nt < 8; nt++) {
                    int col = nt * 8 + t * 2;
                    if (qi0 < Tv) {
                        c0p[col] = __uint_as_float(f2tf(c0p[col] + o[nt][0] * inv0));
                        c0p[col + 1] = __uint_as_float(f2tf(c0p[col + 1] + o[nt][1] * inv0));
                    }
                    if (qi1 < Tv) {
                        c1p[col] = __uint_as_float(f2tf(c1p[col] + o[nt][2] * inv1));
                        c1p[col + 1] = __uint_as_float(f2tf(c1p[col + 1] + o[nt][3] * inv1));
                    }
                }
            }
#pragma unroll
            for (int nt = 0; nt < 8; nt++)
#pragma unroll
                for (int r = 0; r < 4; r++) o[nt][r] = 0.f;
            l0 = 0.f;
            l1 = 0.f;
        }
    }
}

// ---------------- launch ------------------------------------------------------
extern "C" void kernel_launch(void* const* d_in, const int* in_sizes, int n_in,
                              void* d_out, int out_size) {
    const float* x    = (const float*)d_in[0];
    const float* wq   = (const float*)d_in[1];
    const float* wdkv = (const float*)d_in[2];
    const float* wuk1 = (const float*)d_in[3];
    const float* wuk2 = (const float*)d_in[4];
    const float* wuk4 = (const float*)d_in[5];
    const float* wuv1 = (const float*)d_in[6];
    const float* wuv2 = (const float*)d_in[7];
    const float* wuv4 = (const float*)d_in[8];
    const float* wout = (const float*)d_in[9];
    const float* bout = (const float*)d_in[10];
    const float* tbl1 = (const float*)d_in[11];
    const float* tbl2 = (const float*)d_in[12];
    const float* tbl4 = (const float*)d_in[13];

    float *q, *lat, *lp2, *lp4, *k, *v, *k2, *v2, *k4, *v4, *ctx, *wc, *xr;
    cudaGetSymbolAddress((void**)&q, g_q);
    cudaGetSymbolAddress((void**)&lat, g_lat);
    cudaGetSymbolAddress((void**)&lp2, g_lp2);
    cudaGetSymbolAddress((void**)&lp4, g_lp4);
    cudaGetSymbolAddress((void**)&k, g_k);
    cudaGetSymbolAddress((void**)&v, g_v);
    cudaGetSymbolAddress((void**)&k2, g_k2);
    cudaGetSymbolAddress((void**)&v2, g_v2);
    cudaGetSymbolAddress((void**)&k4, g_k4);
    cudaGetSymbolAddress((void**)&v4, g_v4);
    cudaGetSymbolAddress((void**)&ctx, g_ctx);
    cudaGetSymbolAddress((void**)&wc, g_wc);
    cudaGetSymbolAddress((void**)&xr, g_xr);

    const int O_WQ = 0, O_WDKV = 589824, O_WUK1 = 786432, O_WUV1 = 983040;
    const int O_WUK2 = 1179648, O_WUV2 = 1376256, O_WUK4 = 1572864, O_WUV4 = 1769472;
    const int O_WOUT = 1966080;

    CvtArgs ca;
    ca.src[0] = wq;   ca.dst[0] = wc + O_WQ;   ca.n[0] = 589824;
    ca.src[1] = wdkv; ca.dst[1] = wc + O_WDKV; ca.n[1] = 196608;
    ca.src[2] = wuk1; ca.dst[2] = wc + O_WUK1; ca.n[2] = 196608;
    ca.src[3] = wuv1; ca.dst[3] = wc + O_WUV1; ca.n[3] = 196608;
    ca.src[4] = wuk2; ca.dst[4] = wc + O_WUK2; ca.n[4] = 196608;
    ca.src[5] = wuv2; ca.dst[5] = wc + O_WUV2; ca.n[5] = 196608;
    ca.src[6] = wuk4; ca.dst[6] = wc + O_WUK4; ca.n[6] = 196608;
    ca.src[7] = wuv4; ca.dst[7] = wc + O_WUV4; ca.n[7] = 196608;
    ca.src[8] = wout; ca.dst[8] = wc + O_WOUT; ca.n[8] = 589824;
    ca.src[9] = x;    ca.dst[9] = xr;          ca.n[9] = Bv * Tv * DMv;

    const int GEMM_SMEM = 26880 * 4;           // 107,520 B (3-stage)
    const int ATT_SMEM = ATT_SMEM_WORDS * 4;   // 107,520 B
    cudaFuncSetAttribute(gemm_tc, cudaFuncAttributeMaxDynamicSharedMemorySize,
                         GEMM_SMEM);
    cudaFuncSetAttribute(attn_fused, cudaFuncAttributeMaxDynamicSharedMemorySize,
                         ATT_SMEM);

    const int MQ = Bv * Tv;  // 9216

    cvtw_kernel<<<512, 256>>>(ca);

    gemm_tc<<<dim3(6, 72), 256, GEMM_SMEM>>>(xr, wc + O_WQ, nullptr, nullptr,
                                             q, nullptr, MQ, DMv, DMv, 1);
    gemm_tc<<<dim3(2, 72), 256, GEMM_SMEM>>>(xr, wc + O_WDKV, nullptr, nullptr,
                                             lat, nullptr, MQ, LDv, DMv, 1);

    gemm_tc<<<dim3(6, 72, 2), 256, GEMM_SMEM>>>(lat, wc + O_WUK1, wc + O_WUV1,
                                                nullptr, k, v, MQ, DMv, LDv, 1);

    pool_kernel<<<(Bv * 144 * LDv + 255) / 256, 256>>>(lat, lp2, 2, 12, Bv * 144 * LDv);
    gemm_tc<<<dim3(6, 18, 2), 256, GEMM_SMEM>>>(lp2, wc + O_WUK2, wc + O_WUV2,
                                                nullptr, k2, v2, Bv * 144, DMv, LDv, 1);

    pool_kernel<<<(Bv * 36 * LDv + 255) / 256, 256>>>(lat, lp4, 4, 6, Bv * 36 * LDv);
    gemm_tc<<<dim3(6, 5, 2), 256, GEMM_SMEM>>>(lp4, wc + O_WUK4, wc + O_WUV4,
                                               nullptr, k4, v4, Bv * 36, DMv, LDv, 1);

    attn_fused<<<dim3(5, NHv, Bv), 256, ATT_SMEM>>>(q, k, v, k2, v2, k4, v4,
                                                    tbl1, tbl2, tbl4, ctx);

    gemm_tc<<<dim3(6, 72), 256, GEMM_SMEM>>>(ctx, wc + O_WOUT, nullptr, bout,
                                             (float*)d_out, nullptr, MQ, DMv, DMv, 0);
}

// round 9
// speedup vs baseline: 1.5351x; 1.2032x over previous
#include <cuda_runtime.h>
#include <cuda_fp16.h>
#include <cstdint>
#include <cstddef>

#define Bv 16
#define Tv 576
#define NHv 12
#define HDv 64
#define DMv 768
#define LDv 256

// ---------------- scratch (static device allocations; no cudaMalloc) ---------
__device__ __half g_qh[Bv * Tv * DMv];
__device__ float g_lat[Bv * Tv * LDv];
__device__ float g_lp2[Bv * 144 * LDv];
__device__ float g_lp4[Bv * 36 * LDv];
__device__ __half g_kh[Bv * Tv * DMv];
__device__ __half g_vh[Bv * Tv * DMv];
__device__ __half g_k2h[Bv * 144 * DMv];
__device__ __half g_v2h[Bv * 144 * DMv];
__device__ __half g_k4h[Bv * 36 * DMv];
__device__ __half g_v4h[Bv * 36 * DMv];
__device__ float g_ctx[Bv * Tv * DMv];
__device__ float g_wc[2555904];          // tf32-rounded weights
__device__ float g_xr[Bv * Tv * DMv];    // tf32-rounded x

// ---------------- helpers -----------------------------------------------------
__device__ __forceinline__ uint32_t f2tf(float f) {
    uint32_t u;
    asm("cvt.rna.tf32.f32 %0, %1;" : "=r"(u) : "f"(f));
    return u;
}
__device__ __forceinline__ uint32_t pack_f16x2(float lo, float hi) {
    uint32_t u;
    asm("cvt.rn.f16x2.f32 %0, %1, %2;" : "=r"(u) : "f"(hi), "f"(lo));
    return u;
}

__device__ __forceinline__ void mma_tf32(float& c0, float& c1, float& c2, float& c3,
                                         uint32_t a0, uint32_t a1, uint32_t a2, uint32_t a3,
                                         uint32_t b0, uint32_t b1) {
    asm volatile(
        "mma.sync.aligned.m16n8k8.row.col.f32.tf32.tf32.f32 "
        "{%0,%1,%2,%3}, {%4,%5,%6,%7}, {%8,%9}, {%0,%1,%2,%3};"
        : "+f"(c0), "+f"(c1), "+f"(c2), "+f"(c3)
        : "r"(a0), "r"(a1), "r"(a2), "r"(a3), "r"(b0), "r"(b1));
}
__device__ __forceinline__ void mma_f16(float& c0, float& c1, float& c2, float& c3,
                                        uint32_t a0, uint32_t a1, uint32_t a2, uint32_t a3,
                                        uint32_t b0, uint32_t b1) {
    asm volatile(
        "mma.sync.aligned.m16n8k16.row.col.f32.f16.f16.f32 "
        "{%0,%1,%2,%3}, {%4,%5,%6,%7}, {%8,%9}, {%0,%1,%2,%3};"
        : "+f"(c0), "+f"(c1), "+f"(c2), "+f"(c3)
        : "r"(a0), "r"(a1), "r"(a2), "r"(a3), "r"(b0), "r"(b1));
}

__device__ __forceinline__ void ldsm4(uint32_t& r0, uint32_t& r1, uint32_t& r2,
                                      uint32_t& r3, uint32_t addr) {
    asm volatile("ldmatrix.sync.aligned.m8n8.x4.shared.b16 {%0,%1,%2,%3}, [%4];"
                 : "=r"(r0), "=r"(r1), "=r"(r2), "=r"(r3) : "r"(addr));
}
__device__ __forceinline__ void ldsm4t(uint32_t& r0, uint32_t& r1, uint32_t& r2,
                                       uint32_t& r3, uint32_t addr) {
    asm volatile("ldmatrix.sync.aligned.m8n8.x4.trans.shared.b16 {%0,%1,%2,%3}, [%4];"
                 : "=r"(r0), "=r"(r1), "=r"(r2), "=r"(r3) : "r"(addr));
}

__device__ __forceinline__ void cpa16(uint32_t dst, const void* src) {
    asm volatile("cp.async.cg.shared.global [%0], [%1], 16;" :: "r"(dst), "l"(src));
}
__device__ __forceinline__ void cpa16z(uint32_t dst, const void* src, int pred) {
    asm volatile(
        "{\n\t.reg .pred p;\n\tsetp.ne.b32 p, %2, 0;\n\t"
        "@p cp.async.cg.shared.global [%0], [%1], 16;\n\t"
        "@!p cp.async.cg.shared.global [%0], [%1], 16, 0;\n\t}"
        :: "r"(dst), "l"(src), "r"(pred));
}
__device__ __forceinline__ void cp_commit() { asm volatile("cp.async.commit_group;"); }
__device__ __forceinline__ void cp_wait0() { asm volatile("cp.async.wait_group 0;"); }
__device__ __forceinline__ void cp_wait1() { asm volatile("cp.async.wait_group 1;"); }

// ---------------- tf32 pre-rounding (weights + x) ------------------------------
struct CvtArgs {
    const float* src[10];
    float* dst[10];
    int n[10];
};
__global__ void cvtw_kernel(CvtArgs a) {
    int gid = blockIdx.x * blockDim.x + threadIdx.x;
    int stride = gridDim.x * blockDim.x;
#pragma unroll
    for (int s = 0; s < 10; s++) {
        const float* sp = a.src[s];
        float* dp = a.dst[s];
        int n = a.n[s];
        for (int i = gid; i < n; i += stride)
            dp[i] = __uint_as_float(f2tf(sp[i]));
    }
}

// ---------------- tf32 tensor-core GEMM, 3-stage cp.async, BK=32 ---------------
// outmode: 0 = fp32 + bias; 1 = fp32 tf32-rounded; 2 = fp16 (half* outputs).
__global__ __launch_bounds__(256, 2) void gemm_tc(
    const float* __restrict__ A, const float* __restrict__ Bw,
    const float* __restrict__ B2, const float* __restrict__ bias,
    void* __restrict__ Cv, void* __restrict__ C2v,
    int M, int N, int K, int outmode) {
    if (blockIdx.z == 1) { Bw = B2; Cv = C2v; }

    extern __shared__ uint32_t sm[];
    const int bm = blockIdx.y * 128;
    const int bn = blockIdx.x * 128;
    const int tid = threadIdx.x;
    const int lane = tid & 31;
    const int warp = tid >> 5;
    const int wm = (warp & 1) * 64;
    const int wn = (warp >> 1) * 32;
    const int g = lane >> 2;
    const int t = lane & 3;
    const int nk = K >> 5;
    uint32_t sb = (uint32_t)__cvta_generic_to_shared(sm);

    auto issue = [&](int it) {
        int buf = it % 3;
        int k0 = it << 5;
#pragma unroll
        for (int u = 0; u < 4; u++) {
            int idx = u * 256 + tid;
            int r = idx >> 3;
            int c4 = (idx & 7) << 2;
            int pred = (bm + r) < M;
            cpa16z(sb + (buf * 4608 + r * 36 + c4) * 4,
                   A + (size_t)(bm + r) * K + k0 + c4, pred);
        }
#pragma unroll
        for (int u = 0; u < 4; u++) {
            int idx = u * 256 + tid;
            int kk = idx >> 5;
            int c4 = (idx & 31) << 2;
            cpa16(sb + (13824 + buf * 4352 + kk * 136 + c4) * 4,
                  Bw + (size_t)(k0 + kk) * N + bn + c4);
        }
        cp_commit();
    };

    float c[4][4][4];
#pragma unroll
    for (int mt = 0; mt < 4; mt++)
#pragma unroll
        for (int nt = 0; nt < 4; nt++)
#pragma unroll
            for (int r = 0; r < 4; r++) c[mt][nt][r] = 0.f;

    issue(0);
    issue(1);

    for (int it = 0; it < nk; it++) {
        if (it + 1 < nk) cp_wait1(); else cp_wait0();
        __syncthreads();
        if (it + 2 < nk) issue(it + 2);
        const uint32_t* Ab = sm + (it % 3) * 4608;
        const uint32_t* Bb = sm + 13824 + (it % 3) * 4352;
#pragma unroll
        for (int ks = 0; ks < 4; ks++) {
            uint32_t af[4][4], bf[4][2];
#pragma unroll
            for (int mt = 0; mt < 4; mt++) {
                int r = wm + mt * 16 + g;
                af[mt][0] = Ab[r * 36 + ks * 8 + t];
                af[mt][1] = Ab[(r + 8) * 36 + ks * 8 + t];
                af[mt][2] = Ab[r * 36 + ks * 8 + t + 4];
                af[mt][3] = Ab[(r + 8) * 36 + ks * 8 + t + 4];
            }
#pragma unroll
            for (int nt = 0; nt < 4; nt++) {
                int col = wn + nt * 8 + g;
                bf[nt][0] = Bb[(ks * 8 + t) * 136 + col];
                bf[nt][1] = Bb[(ks * 8 + t + 4) * 136 + col];
            }
#pragma unroll
            for (int mt = 0; mt < 4; mt++)
#pragma unroll
                for (int nt = 0; nt < 4; nt++)
                    mma_tf32(c[mt][nt][0], c[mt][nt][1], c[mt][nt][2], c[mt][nt][3],
                             af[mt][0], af[mt][1], af[mt][2], af[mt][3],
                             bf[nt][0], bf[nt][1]);
        }
        __syncthreads();
    }

#pragma unroll
    for (int mt = 0; mt < 4; mt++) {
#pragma unroll
        for (int nt = 0; nt < 4; nt++) {
            int row0 = bm + wm + mt * 16 + g;
            int col = bn + wn + nt * 8 + t * 2;
            if (outmode == 2) {
                __half* Ch = (__half*)Cv;
                uint32_t h01 = pack_f16x2(c[mt][nt][0], c[mt][nt][1]);
                uint32_t h23 = pack_f16x2(c[mt][nt][2], c[mt][nt][3]);
                if (row0 < M) *(uint32_t*)(Ch + (size_t)row0 * N + col) = h01;
                if (row0 + 8 < M) *(uint32_t*)(Ch + (size_t)(row0 + 8) * N + col) = h23;
            } else {
                float* C = (float*)Cv;
                float b0 = bias ? bias[col] : 0.f;
                float b1 = bias ? bias[col + 1] : 0.f;
                float v0 = c[mt][nt][0] + b0, v1 = c[mt][nt][1] + b1;
                float v2 = c[mt][nt][2] + b0, v3 = c[mt][nt][3] + b1;
                if (outmode == 1) {
                    v0 = __uint_as_float(f2tf(v0)); v1 = __uint_as_float(f2tf(v1));
                    v2 = __uint_as_float(f2tf(v2)); v3 = __uint_as_float(f2tf(v3));
                }
                if (row0 < M) *(float2*)(C + (size_t)row0 * N + col) = make_float2(v0, v1);
                if (row0 + 8 < M) *(float2*)(C + (size_t)(row0 + 8) * N + col) = make_float2(v2, v3);
            }
        }
    }
}

// ---------------- exact sxs mean pooling (tf32-rounded output) ------------------
__global__ void pool_kernel(const float* __restrict__ lat, float* __restrict__ out,
                            int s, int g, int n) {
    int idx = blockIdx.x * blockDim.x + threadIdx.x;
    if (idx >= n) return;
    int c = idx & (LDv - 1);
    int rest = idx >> 8;
    int cell = rest % (g * g);
    int b = rest / (g * g);
    int gh = cell / g, gw = cell % g;
    float sum = 0.f;
    for (int i = 0; i < s; i++)
        for (int j = 0; j < s; j++)
            sum += lat[((size_t)(b * Tv) + (gh * s + i) * 24 + (gw * s + j)) * LDv + c];
    out[idx] = __uint_as_float(f2tf(sum / (float)(s * s)));
}

// ---------------- fused 3-scale fp16 flash attention, ldmatrix -----------------
// 128 q-rows per block, 256 threads (8 warps x 16 rows). fp16 Q/K/V via cp.async,
// mma.m16n8k16.f16 with fp32 accumulate, fp32 softmax. K frags via ldmatrix,
// V frags via ldmatrix.trans, P packed register->register (no smem).
// smem words: Ks 2x64x18 [0,2304x2), Vs [4608,+4608), Qs 128x18 [9216,+4608),
//             khcs/kwcs [13824,+256). Rows padded to 72 halves (36 words).
#define ATT_SMEM_WORDS 14080

__global__ __launch_bounds__(256, 2) void attn_fused(
    const __half* __restrict__ qbuf,
    const __half* __restrict__ k1, const __half* __restrict__ v1,
    const __half* __restrict__ k2, const __half* __restrict__ v2,
    const __half* __restrict__ k4, const __half* __restrict__ v4,
    const float* __restrict__ tbl1, const float* __restrict__ tbl2,
    const float* __restrict__ tbl4, float* __restrict__ ctx) {
    extern __shared__ uint32_t smu[];
    float* khcs = (float*)(smu + 13824);  // [2][64]
    float* kwcs = khcs + 128;             // [2][64]
    uint32_t sb = (uint32_t)__cvta_generic_to_shared(smu);

    const int b = blockIdx.z;
    const int h = blockIdx.y;
    const int q0 = blockIdx.x * 128;
    const int tid = threadIdx.x;
    const int lane = tid & 31;
    const int w = tid >> 5;
    const int g = lane >> 2;
    const int t = lane & 3;
    const int lr0 = w * 16 + g;
    const int lr1 = lr0 + 8;

    auto issue_kv = [&](int vt) {
        const __half *kb, *vb;
        int Kt, kt;
        if (vt < 9) {
            kb = k1 + (size_t)b * 576 * DMv + h * HDv;
            vb = v1 + (size_t)b * 576 * DMv + h * HDv;
            Kt = 576; kt = vt;
        } else if (vt < 12) {
            kb = k2 + (size_t)b * 144 * DMv + h * HDv;
            vb = v2 + (size_t)b * 144 * DMv + h * HDv;
            Kt = 144; kt = vt - 9;
        } else {
            kb = k4 + (size_t)b * 36 * DMv + h * HDv;
            vb = v4 + (size_t)b * 36 * DMv + h * HDv;
            Kt = 36; kt = 0;
        }
        int buf = vt & 1;
#pragma unroll
        for (int u = 0; u < 2; u++) {
            int idx = u * 256 + tid;
            int r = idx >> 3;              // key row 0..63
            int c8 = (idx & 7) << 3;       // half col 0..56
            int kg = kt * 64 + r;
            int pred = kg < Kt;
            cpa16z(sb + (buf * 2304 + r * 36 + (c8 >> 1)) * 4,
                   kb + (size_t)kg * DMv + c8, pred);
            cpa16z(sb + (4608 + buf * 2304 + r * 36 + (c8 >> 1)) * 4,
                   vb + (size_t)kg * DMv + c8, pred);
        }
    };

    // stage Q (128 rows x 64 halves), clamp tail rows
    const __half* qsrc = qbuf + (size_t)(b * Tv) * DMv + h * HDv;
#pragma unroll
    for (int u = 0; u < 4; u++) {
        int idx = u * 256 + tid;
        int r = idx >> 3;
        int c8 = (idx & 7) << 3;
        int row = q0 + r;
        if (row > Tv - 1) row = Tv - 1;
        *(uint4*)&smu[9216 + r * 36 + (c8 >> 1)] =
            *(const uint4*)(qsrc + (size_t)row * DMv + c8);
    }
    issue_kv(0);
    cp_commit();
    __syncthreads();

    // hoist Q fragments (fp16 m16n8k16 A-frags): qf[ks][0..3]
    uint32_t qf[4][4];
#pragma unroll
    for (int ks = 0; ks < 4; ks++) {
        qf[ks][0] = smu[9216 + lr0 * 36 + ks * 8 + t];
        qf[ks][1] = smu[9216 + lr1 * 36 + ks * 8 + t];
        qf[ks][2] = smu[9216 + lr0 * 36 + ks * 8 + t + 4];
        qf[ks][3] = smu[9216 + lr1 * 36 + ks * 8 + t + 4];
    }

    float o[8][4];
#pragma unroll
    for (int nt = 0; nt < 8; nt++)
#pragma unroll
        for (int r = 0; r < 4; r++) o[nt][r] = 0.f;
    float l0 = 0.f, l1 = 0.f;

    const float scl = 0.125f;
    const int qi0 = q0 + lr0;
    const int qi1 = q0 + lr1;
    const int qc0 = qi0 < Tv ? qi0 : Tv - 1;
    const int qc1 = qi1 < Tv ? qi1 : Tv - 1;
    const float qh0 = (float)(qc0 / 24), qw0 = (float)(qc0 % 24);
    const float qh1 = (float)(qc1 / 24), qw1 = (float)(qc1 % 24);
    float* c0p = ctx + ((size_t)(b * Tv + qc0)) * DMv + h * HDv;
    float* c1p = ctx + ((size_t)(b * Tv + qc1)) * DMv + h * HDv;

    // per-lane ldmatrix base addresses (byte offsets into shared window)
    const uint32_t krow = sb + (((lane & 7) * 36) + ((lane >> 3) << 2)) * 4;
    const uint32_t vrow = sb + 4608 * 4 +
        (((((lane >> 3) & 1) * 8 + (lane & 7)) * 36) + ((lane >> 4) << 2)) * 4;

    for (int vt = 0; vt < 13; vt++) {
        int seg, Kt, kt, gw_, s_, tw_;
        const float* tb;
        if (vt < 9)       { seg = 0; Kt = 576; kt = vt;      gw_ = 24; s_ = 1; tw_ = 47; tb = tbl1 + h * (47 * 47); }
        else if (vt < 12) { seg = 1; Kt = 144; kt = vt - 9;  gw_ = 12; s_ = 2; tw_ = 23; tb = tbl2 + h * (47 * 23); }
        else              { seg = 2; Kt = 36;  kt = 0;       gw_ = 6;  s_ = 4; tw_ = 11; tb = tbl4 + h * (47 * 11); }
        const float hctr = 0.5f * (float)(s_ - 1);
        const int buf = vt & 1;

        cp_wait0();
        if (tid < 64) {
            int kg = kt * 64 + tid;
            if (kg < Kt) {
                khcs[buf * 64 + tid] = (float)((kg / gw_) * s_) + hctr;
                kwcs[buf * 64 + tid] = (float)((kg % gw_) * s_) + hctr;
            }
        }
        __syncthreads();
        if (vt + 1 < 13) { issue_kv(vt + 1); cp_commit(); }

        const uint32_t kbase = krow + (buf * 2304) * 4;
        const uint32_t vbase = vrow + (buf * 2304) * 4;

        // ---- per n-tile: QK^T mma, bias + exp, pack P to registers ----
        uint32_t pA[8], pB[8];
#pragma unroll
        for (int nt = 0; nt < 8; nt++) {
            uint32_t r0, r1, r2, r3, r4, r5, r6, r7;
            ldsm4(r0, r1, r2, r3, kbase + (nt * 8 * 36) * 4);
            ldsm4(r4, r5, r6, r7, kbase + (nt * 8 * 36) * 4 + 64);
            float s0 = 0.f, s1 = 0.f, s2 = 0.f, s3 = 0.f;
            mma_f16(s0, s1, s2, s3, qf[0][0], qf[0][1], qf[0][2], qf[0][3], r0, r1);
            mma_f16(s0, s1, s2, s3, qf[1][0], qf[1][1], qf[1][2], qf[1][3], r2, r3);
            mma_f16(s0, s1, s2, s3, qf[2][0], qf[2][1], qf[2][2], qf[2][3], r4, r5);
            mma_f16(s0, s1, s2, s3, qf[3][0], qf[3][1], qf[3][2], qf[3][3], r6, r7);

            int lc = nt * 8 + t * 2;
            int kg = kt * 64 + lc;
            float p0 = 0.f, p1 = 0.f, p2 = 0.f, p3 = 0.f;
            if (kg < Kt) {  // Kt even => kg+1 also valid
                float khcA = khcs[buf * 64 + lc], kwcA = kwcs[buf * 64 + lc];
                float khcB = khcs[buf * 64 + lc + 1], kwcB = kwcs[buf * 64 + lc + 1];
                int rh0a = (int)(qh0 - khcA) + 23, rw0a = (int)(qw0 - kwcA) + (gw_ - 1);
                int rh0b = (int)(qh0 - khcB) + 23, rw0b = (int)(qw0 - kwcB) + (gw_ - 1);
                int rh1a = (int)(qh1 - khcA) + 23, rw1a = (int)(qw1 - kwcA) + (gw_ - 1);
                int rh1b = (int)(qh1 - khcB) + 23, rw1b = (int)(qw1 - kwcB) + (gw_ - 1);
                p0 = __expf(s0 * scl + __ldg(&tb[rh0a * tw_ + rw0a]));
                p1 = __expf(s1 * scl + __ldg(&tb[rh0b * tw_ + rw0b]));
                p2 = __expf(s2 * scl + __ldg(&tb[rh1a * tw_ + rw1a]));
                p3 = __expf(s3 * scl + __ldg(&tb[rh1b * tw_ + rw1b]));
            }
            l0 += p0 + p1;
            l1 += p2 + p3;
            pA[nt] = pack_f16x2(p0, p1);
            pB[nt] = pack_f16x2(p2, p3);
        }

        // ---- O += P V  (P in registers, V frags via ldmatrix.trans) ----
#pragma unroll
        for (int ks = 0; ks < 4; ks++) {
            uint32_t a0 = pA[2 * ks], a1 = pB[2 * ks];
            uint32_t a2 = pA[2 * ks + 1], a3 = pB[2 * ks + 1];
#pragma unroll
            for (int p = 0; p < 4; p++) {
                uint32_t v0, v1, v2, v3;
                ldsm4t(v0, v1, v2, v3, vbase + (ks * 16 * 36 + p * 8) * 4);
                mma_f16(o[2 * p][0], o[2 * p][1], o[2 * p][2], o[2 * p][3],
                        a0, a1, a2, a3, v0, v1);
                mma_f16(o[2 * p + 1][0], o[2 * p + 1][1], o[2 * p + 1][2], o[2 * p + 1][3],
                        a0, a1, a2, a3, v2, v3);
            }
        }

        // ---- segment boundary: normalize + write, reset ----
        if (vt == 8 || vt == 11 || vt == 12) {
            float L0 = l0, L1 = l1;
            L0 += __shfl_xor_sync(0xffffffffu, L0, 1);
            L0 += __shfl_xor_sync(0xffffffffu, L0, 2);
            L1 += __shfl_xor_sync(0xffffffffu, L1, 1);
            L1 += __shfl_xor_sync(0xffffffffu, L1, 2);
            float inv0 = 1.f / (3.f * L0);
            float inv1 = 1.f / (3.f * L1);
            if (seg == 0) {
#pragma unroll
                for (int nt = 0; nt < 8; nt++) {
                    int col = nt * 8 + t * 2;
                    if (qi0 < Tv) {
                        c0p[col] = o[nt][0] * inv0;
                        c0p[col + 1] = o[nt][1] * inv0;
                    }
                    if (qi1 < Tv) {
                        c1p[col] = o[nt][2] * inv1;
                        c1p[col + 1] = o[nt][3] * inv1;
                    }
                }
            } else if (seg == 1) {
#pragma unroll
                for (int nt = 0; nt < 8; nt++) {
                    int col = nt * 8 + t * 2;
                    if (qi0 < Tv) {
                        c0p[col] += o[nt][0] * inv0;
                        c0p[col + 1] += o[nt][1] * inv0;
                    }
                    if (qi1 < Tv) {
                        c1p[col] += o[nt][2] * inv1;
                        c1p[col + 1] += o[nt][3] * inv1;
                    }
                }
            } else {
#pragma unroll
                for (int nt = 0; nt < 8; nt++) {
                    int col = nt * 8 + t * 2;
                    if (qi0 < Tv) {
                        c0p[col] = __uint_as_float(f2tf(c0p[col] + o[nt][0] * inv0));
                        c0p[col + 1] = __uint_as_float(f2tf(c0p[col + 1] + o[nt][1] * inv0));
                    }
                    if (qi1 < Tv) {
                        c1p[col] = __uint_as_float(f2tf(c1p[col] + o[nt][2] * inv1));
                        c1p[col + 1] = __uint_as_float(f2tf(c1p[col + 1] + o[nt][3] * inv1));
                    }
                }
            }
#pragma unroll
            for (int nt = 0; nt < 8; nt++)
#pragma unroll
                for (int r = 0; r < 4; r++) o[nt][r] = 0.f;
            l0 = 0.f;
            l1 = 0.f;
        }
    }
}

// ---------------- launch ------------------------------------------------------
extern "C" void kernel_launch(void* const* d_in, const int* in_sizes, int n_in,
                              void* d_out, int out_size) {
    const float* x    = (const float*)d_in[0];
    const float* wq   = (const float*)d_in[1];
    const float* wdkv = (const float*)d_in[2];
    const float* wuk1 = (const float*)d_in[3];
    const float* wuk2 = (const float*)d_in[4];
    const float* wuk4 = (const float*)d_in[5];
    const float* wuv1 = (const float*)d_in[6];
    const float* wuv2 = (const float*)d_in[7];
    const float* wuv4 = (const float*)d_in[8];
    const float* wout = (const float*)d_in[9];
    const float* bout = (const float*)d_in[10];
    const float* tbl1 = (const float*)d_in[11];
    const float* tbl2 = (const float*)d_in[12];
    const float* tbl4 = (const float*)d_in[13];

    float *lat, *lp2, *lp4, *ctx, *wc, *xr;
    __half *qh, *kh, *vh, *k2h, *v2h, *k4h, *v4h;
    cudaGetSymbolAddress((void**)&qh, g_qh);
    cudaGetSymbolAddress((void**)&lat, g_lat);
    cudaGetSymbolAddress((void**)&lp2, g_lp2);
    cudaGetSymbolAddress((void**)&lp4, g_lp4);
    cudaGetSymbolAddress((void**)&kh, g_kh);
    cudaGetSymbolAddress((void**)&vh, g_vh);
    cudaGetSymbolAddress((void**)&k2h, g_k2h);
    cudaGetSymbolAddress((void**)&v2h, g_v2h);
    cudaGetSymbolAddress((void**)&k4h, g_k4h);
    cudaGetSymbolAddress((void**)&v4h, g_v4h);
    cudaGetSymbolAddress((void**)&ctx, g_ctx);
    cudaGetSymbolAddress((void**)&wc, g_wc);
    cudaGetSymbolAddress((void**)&xr, g_xr);

    const int O_WQ = 0, O_WDKV = 589824, O_WUK1 = 786432, O_WUV1 = 983040;
    const int O_WUK2 = 1179648, O_WUV2 = 1376256, O_WUK4 = 1572864, O_WUV4 = 1769472;
    const int O_WOUT = 1966080;

    CvtArgs ca;
    ca.src[0] = wq;   ca.dst[0] = wc + O_WQ;   ca.n[0] = 589824;
    ca.src[1] = wdkv; ca.dst[1] = wc + O_WDKV; ca.n[1] = 196608;
    ca.src[2] = wuk1; ca.dst[2] = wc + O_WUK1; ca.n[2] = 196608;
    ca.src[3] = wuv1; ca.dst[3] = wc + O_WUV1; ca.n[3] = 196608;
    ca.src[4] = wuk2; ca.dst[4] = wc + O_WUK2; ca.n[4] = 196608;
    ca.src[5] = wuv2; ca.dst[5] = wc + O_WUV2; ca.n[5] = 196608;
    ca.src[6] = wuk4; ca.dst[6] = wc + O_WUK4; ca.n[6] = 196608;
    ca.src[7] = wuv4; ca.dst[7] = wc + O_WUV4; ca.n[7] = 196608;
    ca.src[8] = wout; ca.dst[8] = wc + O_WOUT; ca.n[8] = 589824;
    ca.src[9] = x;    ca.dst[9] = xr;          ca.n[9] = Bv * Tv * DMv;

    const int GEMM_SMEM = 26880 * 4;           // 107,520 B
    const int ATT_SMEM = ATT_SMEM_WORDS * 4;   // 56,320 B
    cudaFuncSetAttribute(gemm_tc, cudaFuncAttributeMaxDynamicSharedMemorySize,
                         GEMM_SMEM);
    cudaFuncSetAttribute(attn_fused, cudaFuncAttributeMaxDynamicSharedMemorySize,
                         ATT_SMEM);

    const int MQ = Bv * Tv;  // 9216

    cvtw_kernel<<<512, 256>>>(ca);

    gemm_tc<<<dim3(6, 72), 256, GEMM_SMEM>>>(xr, wc + O_WQ, nullptr, nullptr,
                                             qh, nullptr, MQ, DMv, DMv, 2);
    gemm_tc<<<dim3(2, 72), 256, GEMM_SMEM>>>(xr, wc + O_WDKV, nullptr, nullptr,
                                             lat, nullptr, MQ, LDv, DMv, 1);

    gemm_tc<<<dim3(6, 72, 2), 256, GEMM_SMEM>>>(lat, wc + O_WUK1, wc + O_WUV1,
                                                nullptr, kh, vh, MQ, DMv, LDv, 2);

    pool_kernel<<<(Bv * 144 * LDv + 255) / 256, 256>>>(lat, lp2, 2, 12, Bv * 144 * LDv);
    gemm_tc<<<dim3(6, 18, 2), 256, GEMM_SMEM>>>(lp2, wc + O_WUK2, wc + O_WUV2,
                                                nullptr, k2h, v2h, Bv * 144, DMv, LDv, 2);

    pool_kernel<<<(Bv * 36 * LDv + 255) / 256, 256>>>(lat, lp4, 4, 6, Bv * 36 * LDv);
    gemm_tc<<<dim3(6, 5, 2), 256, GEMM_SMEM>>>(lp4, wc + O_WUK4, wc + O_WUV4,
                                               nullptr, k4h, v4h, Bv * 36, DMv, LDv, 2);

    attn_fused<<<dim3(5, NHv, Bv), 256, ATT_SMEM>>>(qh, kh, vh, k2h, v2h, k4h, v4h,
                                                    tbl1, tbl2, tbl4, ctx);

    gemm_tc<<<dim3(6, 72), 256, GEMM_SMEM>>>(ctx, wc + O_WOUT, nullptr, bout,
                                             (float*)d_out, nullptr, MQ, DMv, DMv, 0);
}

// round 10
// speedup vs baseline: 1.9282x; 1.2560x over previous
#include <cuda_runtime.h>
#include <cuda_fp16.h>
#include <cstdint>
#include <cstddef>

#define Bv 16
#define Tv 576
#define NHv 12
#define HDv 64
#define DMv 768
#define LDv 256

// ---------------- scratch (static device allocations; no cudaMalloc) ---------
__device__ __half g_qh[Bv * Tv * DMv];
__device__ __half g_lath[Bv * Tv * LDv];
__device__ __half g_lp2h[Bv * 144 * LDv];
__device__ __half g_lp4h[Bv * 36 * LDv];
__device__ __half g_kh[Bv * Tv * DMv];
__device__ __half g_vh[Bv * Tv * DMv];
__device__ __half g_k2h[Bv * 144 * DMv];
__device__ __half g_v2h[Bv * 144 * DMv];
__device__ __half g_k4h[Bv * 36 * DMv];
__device__ __half g_v4h[Bv * 36 * DMv];
__device__ float g_ctx[Bv * Tv * DMv];
__device__ __half g_ctxh[Bv * Tv * DMv];
__device__ __half g_wch[2555904];        // fp16 weights
__device__ __half g_xh[Bv * Tv * DMv];   // fp16 x

// ---------------- helpers -----------------------------------------------------
__device__ __forceinline__ uint32_t pack_f16x2(float lo, float hi) {
    uint32_t u;
    asm("cvt.rn.f16x2.f32 %0, %1, %2;" : "=r"(u) : "f"(hi), "f"(lo));
    return u;
}

__device__ __forceinline__ void mma_f16(float& c0, float& c1, float& c2, float& c3,
                                        uint32_t a0, uint32_t a1, uint32_t a2, uint32_t a3,
                                        uint32_t b0, uint32_t b1) {
    asm volatile(
        "mma.sync.aligned.m16n8k16.row.col.f32.f16.f16.f32 "
        "{%0,%1,%2,%3}, {%4,%5,%6,%7}, {%8,%9}, {%0,%1,%2,%3};"
        : "+f"(c0), "+f"(c1), "+f"(c2), "+f"(c3)
        : "r"(a0), "r"(a1), "r"(a2), "r"(a3), "r"(b0), "r"(b1));
}

__device__ __forceinline__ void ldsm4(uint32_t& r0, uint32_t& r1, uint32_t& r2,
                                      uint32_t& r3, uint32_t addr) {
    asm volatile("ldmatrix.sync.aligned.m8n8.x4.shared.b16 {%0,%1,%2,%3}, [%4];"
                 : "=r"(r0), "=r"(r1), "=r"(r2), "=r"(r3) : "r"(addr));
}
__device__ __forceinline__ void ldsm4t(uint32_t& r0, uint32_t& r1, uint32_t& r2,
                                       uint32_t& r3, uint32_t addr) {
    asm volatile("ldmatrix.sync.aligned.m8n8.x4.trans.shared.b16 {%0,%1,%2,%3}, [%4];"
                 : "=r"(r0), "=r"(r1), "=r"(r2), "=r"(r3) : "r"(addr));
}

__device__ __forceinline__ void cpa16(uint32_t dst, const void* src) {
    asm volatile("cp.async.cg.shared.global [%0], [%1], 16;" :: "r"(dst), "l"(src));
}
__device__ __forceinline__ void cpa16z(uint32_t dst, const void* src, int pred) {
    asm volatile(
        "{\n\t.reg .pred p;\n\tsetp.ne.b32 p, %2, 0;\n\t"
        "@p cp.async.cg.shared.global [%0], [%1], 16;\n\t"
        "@!p cp.async.cg.shared.global [%0], [%1], 16, 0;\n\t}"
        :: "r"(dst), "l"(src), "r"(pred));
}
__device__ __forceinline__ void cp_commit() { asm volatile("cp.async.commit_group;"); }
__device__ __forceinline__ void cp_wait0() { asm volatile("cp.async.wait_group 0;"); }
__device__ __forceinline__ void cp_wait1() { asm volatile("cp.async.wait_group 1;"); }

// ---------------- fp16 pre-conversion (weights + x) ----------------------------
struct CvtArgs {
    const float* src[10];
    __half* dst[10];
    int n[10];
};
__global__ void cvtw_kernel(CvtArgs a) {
    int gid = blockIdx.x * blockDim.x + threadIdx.x;
    int stride = gridDim.x * blockDim.x;
#pragma unroll
    for (int s = 0; s < 10; s++) {
        const float* sp = a.src[s];
        __half* dp = a.dst[s];
        int n = a.n[s];
        for (int i = gid; i < n; i += stride)
            dp[i] = __float2half(sp[i]);
    }
}

// ---------------- ctx fp32 -> fp16 ---------------------------------------------
__global__ void cvtctx_kernel(const float* __restrict__ src,
                              __half* __restrict__ dst, int n4) {
    int i = blockIdx.x * blockDim.x + threadIdx.x;
    if (i >= n4) return;
    float4 v = *(const float4*)(src + i * 4);
    uint32_t lo = pack_f16x2(v.x, v.y);
    uint32_t hi = pack_f16x2(v.z, v.w);
    uint2 o; o.x = lo; o.y = hi;
    *(uint2*)(dst + i * 4) = o;
}

// ---------------- fp16 tensor-core GEMM, 3-stage cp.async, BK=64 ---------------
// C(/C2) = A(MxK) * Bw(KxN) (+bias). fp16 in, fp32 accum.
// 128x128 tile, 256 threads (8 warps, warp tile 64x32), mma.m16n8k16.
// smem words: A 3 x 4608 at 0 (rows padded 64->72 halves, stride 36 words);
//             B 3 x 4352 at 13824 (rows padded 128->136 halves, stride 68 words).
// Both strides give bank-disjoint ldmatrix row quads. 107,520 B total.
// fp16out: 0 = fp32 + bias; 1 = fp16 store.
__global__ __launch_bounds__(256, 2) void gemm_fp16(
    const __half* __restrict__ A, const __half* __restrict__ Bw,
    const __half* __restrict__ B2, const float* __restrict__ bias,
    void* __restrict__ Cv, void* __restrict__ C2v,
    int M, int N, int K, int fp16out) {
    if (blockIdx.z == 1) { Bw = B2; Cv = C2v; }

    extern __shared__ uint32_t sm[];
    const int bm = blockIdx.y * 128;
    const int bn = blockIdx.x * 128;
    const int tid = threadIdx.x;
    const int lane = tid & 31;
    const int warp = tid >> 5;
    const int wm = (warp & 1) * 64;
    const int wn = (warp >> 1) * 32;
    const int g = lane >> 2;
    const int t = lane & 3;
    const int nk = K >> 6;
    uint32_t sb = (uint32_t)__cvta_generic_to_shared(sm);

    auto issue = [&](int it) {
        int buf = it % 3;
        int k0 = it << 6;
        // A: 128 rows x 64 halves (8 x 16B chunks per row) = 4 chunks/thread
#pragma unroll
        for (int u = 0; u < 4; u++) {
            int idx = u * 256 + tid;
            int r = idx >> 3;
            int ch = idx & 7;
            int pred = (bm + r) < M;
            cpa16z(sb + (buf * 4608 + r * 36 + ch * 4) * 4,
                   A + (size_t)(bm + r) * K + k0 + ch * 8, pred);
        }
        // B: 64 rows x 128 halves (16 x 16B chunks per row) = 4 chunks/thread
#pragma unroll
        for (int u = 0; u < 4; u++) {
            int idx = u * 256 + tid;
            int kk = idx >> 4;
            int ch = idx & 15;
            cpa16(sb + (13824 + buf * 4352 + kk * 68 + ch * 4) * 4,
                  Bw + (size_t)(k0 + kk) * N + bn + ch * 8);
        }
        cp_commit();
    };

    float c[4][4][4];
#pragma unroll
    for (int mt = 0; mt < 4; mt++)
#pragma unroll
        for (int nt = 0; nt < 4; nt++)
#pragma unroll
            for (int r = 0; r < 4; r++) c[mt][nt][r] = 0.f;

    issue(0);
    issue(1);

    // per-lane ldmatrix byte bases
    const uint32_t aB = sb + (((wm + (lane & 15)) * 36) + (lane >> 4) * 4) * 4;
    const uint32_t bB = sb + 13824 * 4 +
        (((((lane >> 3) & 1) * 8 + (lane & 7)) * 68) + (wn >> 1) + (lane >> 4) * 4) * 4;

    for (int it = 0; it < nk; it++) {
        if (it + 1 < nk) cp_wait1(); else cp_wait0();
        __syncthreads();
        if (it + 2 < nk) issue(it + 2);
        const uint32_t aOff = (uint32_t)((it % 3) * 4608 * 4);
        const uint32_t bOff = (uint32_t)((it % 3) * 4352 * 4);
#pragma unroll
        for (int ks = 0; ks < 4; ks++) {
            uint32_t af[4][4];
#pragma unroll
            for (int mt = 0; mt < 4; mt++)
                ldsm4(af[mt][0], af[mt][1], af[mt][2], af[mt][3],
                      aB + aOff + (uint32_t)((mt * 16 * 36 + ks * 8) * 4));
            uint32_t bf[4][2];
#pragma unroll
            for (int nh = 0; nh < 2; nh++) {
                uint32_t v0, v1, v2, v3;
                ldsm4t(v0, v1, v2, v3,
                       bB + bOff + (uint32_t)((ks * 16 * 68 + nh * 8) * 4));
                bf[nh * 2][0] = v0; bf[nh * 2][1] = v1;
                bf[nh * 2 + 1][0] = v2; bf[nh * 2 + 1][1] = v3;
            }
#pragma unroll
            for (int mt = 0; mt < 4; mt++)
#pragma unroll
                for (int nt = 0; nt < 4; nt++)
                    mma_f16(c[mt][nt][0], c[mt][nt][1], c[mt][nt][2], c[mt][nt][3],
                            af[mt][0], af[mt][1], af[mt][2], af[mt][3],
                            bf[nt][0], bf[nt][1]);
        }
        __syncthreads();
    }

#pragma unroll
    for (int mt = 0; mt < 4; mt++) {
#pragma unroll
        for (int nt = 0; nt < 4; nt++) {
            int row0 = bm + wm + mt * 16 + g;
            int col = bn + wn + nt * 8 + t * 2;
            if (fp16out) {
                __half* Ch = (__half*)Cv;
                uint32_t h01 = pack_f16x2(c[mt][nt][0], c[mt][nt][1]);
                uint32_t h23 = pack_f16x2(c[mt][nt][2], c[mt][nt][3]);
                if (row0 < M) *(uint32_t*)(Ch + (size_t)row0 * N + col) = h01;
                if (row0 + 8 < M) *(uint32_t*)(Ch + (size_t)(row0 + 8) * N + col) = h23;
            } else {
                float* C = (float*)Cv;
                float b0 = bias ? bias[col] : 0.f;
                float b1 = bias ? bias[col + 1] : 0.f;
                if (row0 < M)
                    *(float2*)(C + (size_t)row0 * N + col) =
                        make_float2(c[mt][nt][0] + b0, c[mt][nt][1] + b1);
                if (row0 + 8 < M)
                    *(float2*)(C + (size_t)(row0 + 8) * N + col) =
                        make_float2(c[mt][nt][2] + b0, c[mt][nt][3] + b1);
            }
        }
    }
}

// ---------------- exact sxs mean pooling (fp16 in/out, fp32 sum) ---------------
__global__ void pool_kernel(const __half* __restrict__ lat, __half* __restrict__ out,
                            int s, int g, int n) {
    int idx = blockIdx.x * blockDim.x + threadIdx.x;
    if (idx >= n) return;
    int c = idx & (LDv - 1);
    int rest = idx >> 8;
    int cell = rest % (g * g);
    int b = rest / (g * g);
    int gh = cell / g, gw = cell % g;
    float sum = 0.f;
    for (int i = 0; i < s; i++)
        for (int j = 0; j < s; j++)
            sum += __half2float(
                lat[((size_t)(b * Tv) + (gh * s + i) * 24 + (gw * s + j)) * LDv + c]);
    out[idx] = __float2half(sum / (float)(s * s));
}

// ---------------- fused 3-scale fp16 flash attention (R9 version) --------------
// ctx written as plain fp32 (fp16 conversion happens in cvtctx_kernel).
#define ATT_SMEM_WORDS 14080

__global__ __launch_bounds__(256, 2) void attn_fused(
    const __half* __restrict__ qbuf,
    const __half* __restrict__ k1, const __half* __restrict__ v1,
    const __half* __restrict__ k2, const __half* __restrict__ v2,
    const __half* __restrict__ k4, const __half* __restrict__ v4,
    const float* __restrict__ tbl1, const float* __restrict__ tbl2,
    const float* __restrict__ tbl4, float* __restrict__ ctx) {
    extern __shared__ uint32_t smu[];
    float* khcs = (float*)(smu + 13824);
    float* kwcs = khcs + 128;
    uint32_t sb = (uint32_t)__cvta_generic_to_shared(smu);

    const int b = blockIdx.z;
    const int h = blockIdx.y;
    const int q0 = blockIdx.x * 128;
    const int tid = threadIdx.x;
    const int lane = tid & 31;
    const int w = tid >> 5;
    const int g = lane >> 2;
    const int t = lane & 3;
    const int lr0 = w * 16 + g;
    const int lr1 = lr0 + 8;

    auto issue_kv = [&](int vt) {
        const __half *kb, *vb;
        int Kt, kt;
        if (vt < 9) {
            kb = k1 + (size_t)b * 576 * DMv + h * HDv;
            vb = v1 + (size_t)b * 576 * DMv + h * HDv;
            Kt = 576; kt = vt;
        } else if (vt < 12) {
            kb = k2 + (size_t)b * 144 * DMv + h * HDv;
            vb = v2 + (size_t)b * 144 * DMv + h * HDv;
            Kt = 144; kt = vt - 9;
        } else {
            kb = k4 + (size_t)b * 36 * DMv + h * HDv;
            vb = v4 + (size_t)b * 36 * DMv + h * HDv;
            Kt = 36; kt = 0;
        }
        int buf = vt & 1;
#pragma unroll
        for (int u = 0; u < 2; u++) {
            int idx = u * 256 + tid;
            int r = idx >> 3;
            int c8 = (idx & 7) << 3;
            int kg = kt * 64 + r;
            int pred = kg < Kt;
            cpa16z(sb + (buf * 2304 + r * 36 + (c8 >> 1)) * 4,
                   kb + (size_t)kg * DMv + c8, pred);
            cpa16z(sb + (4608 + buf * 2304 + r * 36 + (c8 >> 1)) * 4,
                   vb + (size_t)kg * DMv + c8, pred);
        }
    };

    const __half* qsrc = qbuf + (size_t)(b * Tv) * DMv + h * HDv;
#pragma unroll
    for (int u = 0; u < 4; u++) {
        int idx = u * 256 + tid;
        int r = idx >> 3;
        int c8 = (idx & 7) << 3;
        int row = q0 + r;
        if (row > Tv - 1) row = Tv - 1;
        *(uint4*)&smu[9216 + r * 36 + (c8 >> 1)] =
            *(const uint4*)(qsrc + (size_t)row * DMv + c8);
    }
    issue_kv(0);
    cp_commit();
    __syncthreads();

    uint32_t qf[4][4];
#pragma unroll
    for (int ks = 0; ks < 4; ks++) {
        qf[ks][0] = smu[9216 + lr0 * 36 + ks * 8 + t];
        qf[ks][1] = smu[9216 + lr1 * 36 + ks * 8 + t];
        qf[ks][2] = smu[9216 + lr0 * 36 + ks * 8 + t + 4];
        qf[ks][3] = smu[9216 + lr1 * 36 + ks * 8 + t + 4];
    }

    float o[8][4];
#pragma unroll
    for (int nt = 0; nt < 8; nt++)
#pragma unroll
        for (int r = 0; r < 4; r++) o[nt][r] = 0.f;
    float l0 = 0.f, l1 = 0.f;

    const float scl = 0.125f;
    const int qi0 = q0 + lr0;
    const int qi1 = q0 + lr1;
    const int qc0 = qi0 < Tv ? qi0 : Tv - 1;
    const int qc1 = qi1 < Tv ? qi1 : Tv - 1;
    const float qh0 = (float)(qc0 / 24), qw0 = (float)(qc0 % 24);
    const float qh1 = (float)(qc1 / 24), qw1 = (float)(qc1 % 24);
    float* c0p = ctx + ((size_t)(b * Tv + qc0)) * DMv + h * HDv;
    float* c1p = ctx + ((size_t)(b * Tv + qc1)) * DMv + h * HDv;

    const uint32_t krow = sb + (((lane & 7) * 36) + ((lane >> 3) << 2)) * 4;
    const uint32_t vrow = sb + 4608 * 4 +
        (((((lane >> 3) & 1) * 8 + (lane & 7)) * 36) + ((lane >> 4) << 2)) * 4;

    for (int vt = 0; vt < 13; vt++) {
        int seg, Kt, kt, gw_, s_, tw_;
        const float* tb;
        if (vt < 9)       { seg = 0; Kt = 576; kt = vt;      gw_ = 24; s_ = 1; tw_ = 47; tb = tbl1 + h * (47 * 47); }
        else if (vt < 12) { seg = 1; Kt = 144; kt = vt - 9;  gw_ = 12; s_ = 2; tw_ = 23; tb = tbl2 + h * (47 * 23); }
        else              { seg = 2; Kt = 36;  kt = 0;       gw_ = 6;  s_ = 4; tw_ = 11; tb = tbl4 + h * (47 * 11); }
        const float hctr = 0.5f * (float)(s_ - 1);
        const int buf = vt & 1;

        cp_wait0();
        if (tid < 64) {
            int kg = kt * 64 + tid;
            if (kg < Kt) {
                khcs[buf * 64 + tid] = (float)((kg / gw_) * s_) + hctr;
                kwcs[buf * 64 + tid] = (float)((kg % gw_) * s_) + hctr;
            }
        }
        __syncthreads();
        if (vt + 1 < 13) { issue_kv(vt + 1); cp_commit(); }

        const uint32_t kbase = krow + (buf * 2304) * 4;
        const uint32_t vbase = vrow + (buf * 2304) * 4;

        uint32_t pA[8], pB[8];
#pragma unroll
        for (int nt = 0; nt < 8; nt++) {
            uint32_t r0, r1, r2, r3, r4, r5, r6, r7;
            ldsm4(r0, r1, r2, r3, kbase + (nt * 8 * 36) * 4);
            ldsm4(r4, r5, r6, r7, kbase + (nt * 8 * 36) * 4 + 64);
            float s0 = 0.f, s1 = 0.f, s2 = 0.f, s3 = 0.f;
            mma_f16(s0, s1, s2, s3, qf[0][0], qf[0][1], qf[0][2], qf[0][3], r0, r1);
            mma_f16(s0, s1, s2, s3, qf[1][0], qf[1][1], qf[1][2], qf[1][3], r2, r3);
            mma_f16(s0, s1, s2, s3, qf[2][0], qf[2][1], qf[2][2], qf[2][3], r4, r5);
            mma_f16(s0, s1, s2, s3, qf[3][0], qf[3][1], qf[3][2], qf[3][3], r6, r7);

            int lc = nt * 8 + t * 2;
            int kg = kt * 64 + lc;
            float p0 = 0.f, p1 = 0.f, p2 = 0.f, p3 = 0.f;
            if (kg < Kt) {
                float khcA = khcs[buf * 64 + lc], kwcA = kwcs[buf * 64 + lc];
                float khcB = khcs[buf * 64 + lc + 1], kwcB = kwcs[buf * 64 + lc + 1];
                int rh0a = (int)(qh0 - khcA) + 23, rw0a = (int)(qw0 - kwcA) + (gw_ - 1);
                int rh0b = (int)(qh0 - khcB) + 23, rw0b = (int)(qw0 - kwcB) + (gw_ - 1);
                int rh1a = (int)(qh1 - khcA) + 23, rw1a = (int)(qw1 - kwcA) + (gw_ - 1);
                int rh1b = (int)(qh1 - khcB) + 23, rw1b = (int)(qw1 - kwcB) + (gw_ - 1);
                p0 = __expf(s0 * scl + __ldg(&tb[rh0a * tw_ + rw0a]));
                p1 = __expf(s1 * scl + __ldg(&tb[rh0b * tw_ + rw0b]));
                p2 = __expf(s2 * scl + __ldg(&tb[rh1a * tw_ + rw1a]));
                p3 = __expf(s3 * scl + __ldg(&tb[rh1b * tw_ + rw1b]));
            }
            l0 += p0 + p1;
            l1 += p2 + p3;
            pA[nt] = pack_f16x2(p0, p1);
            pB[nt] = pack_f16x2(p2, p3);
        }

#pragma unroll
        for (int ks = 0; ks < 4; ks++) {
            uint32_t a0 = pA[2 * ks], a1 = pB[2 * ks];
            uint32_t a2 = pA[2 * ks + 1], a3 = pB[2 * ks + 1];
#pragma unroll
            for (int p = 0; p < 4; p++) {
                uint32_t v0, v1, v2, v3;
                ldsm4t(v0, v1, v2, v3, vbase + (ks * 16 * 36 + p * 8) * 4);
                mma_f16(o[2 * p][0], o[2 * p][1], o[2 * p][2], o[2 * p][3],
                        a0, a1, a2, a3, v0, v1);
                mma_f16(o[2 * p + 1][0], o[2 * p + 1][1], o[2 * p + 1][2], o[2 * p + 1][3],
                        a0, a1, a2, a3, v2, v3);
            }
        }

        if (vt == 8 || vt == 11 || vt == 12) {
            float L0 = l0, L1 = l1;
            L0 += __shfl_xor_sync(0xffffffffu, L0, 1);
            L0 += __shfl_xor_sync(0xffffffffu, L0, 2);
            L1 += __shfl_xor_sync(0xffffffffu, L1, 1);
            L1 += __shfl_xor_sync(0xffffffffu, L1, 2);
            float inv0 = 1.f / (3.f * L0);
            float inv1 = 1.f / (3.f * L1);
            if (seg == 0) {
#pragma unroll
                for (int nt = 0; nt < 8; nt++) {
                    int col = nt * 8 + t * 2;
                    if (qi0 < Tv) {
                        c0p[col] = o[nt][0] * inv0;
                        c0p[col + 1] = o[nt][1] * inv0;
                    }
                    if (qi1 < Tv) {
                        c1p[col] = o[nt][2] * inv1;
                        c1p[col + 1] = o[nt][3] * inv1;
                    }
                }
            } else {
#pragma unroll
                for (int nt = 0; nt < 8; nt++) {
                    int col = nt * 8 + t * 2;
                    if (qi0 < Tv) {
                        c0p[col] += o[nt][0] * inv0;
                        c0p[col + 1] += o[nt][1] * inv0;
                    }
                    if (qi1 < Tv) {
                        c1p[col] += o[nt][2] * inv1;
                        c1p[col + 1] += o[nt][3] * inv1;
                    }
                }
            }
#pragma unroll
            for (int nt = 0; nt < 8; nt++)
#pragma unroll
                for (int r = 0; r < 4; r++) o[nt][r] = 0.f;
            l0 = 0.f;
            l1 = 0.f;
        }
    }
}

// ---------------- launch ------------------------------------------------------
extern "C" void kernel_launch(void* const* d_in, const int* in_sizes, int n_in,
                              void* d_out, int out_size) {
    const float* x    = (const float*)d_in[0];
    const float* wq   = (const float*)d_in[1];
    const float* wdkv = (const float*)d_in[2];
    const float* wuk1 = (const float*)d_in[3];
    const float* wuk2 = (const float*)d_in[4];
    const float* wuk4 = (const float*)d_in[5];
    const float* wuv1 = (const float*)d_in[6];
    const float* wuv2 = (const float*)d_in[7];
    const float* wuv4 = (const float*)d_in[8];
    const float* wout = (const float*)d_in[9];
    const float* bout = (const float*)d_in[10];
    const float* tbl1 = (const float*)d_in[11];
    const float* tbl2 = (const float*)d_in[12];
    const float* tbl4 = (const float*)d_in[13];

    float* ctx;
    __half *qh, *lath, *lp2h, *lp4h, *kh, *vh, *k2h, *v2h, *k4h, *v4h, *wch, *xh, *ctxh;
    cudaGetSymbolAddress((void**)&qh, g_qh);
    cudaGetSymbolAddress((void**)&lath, g_lath);
    cudaGetSymbolAddress((void**)&lp2h, g_lp2h);
    cudaGetSymbolAddress((void**)&lp4h, g_lp4h);
    cudaGetSymbolAddress((void**)&kh, g_kh);
    cudaGetSymbolAddress((void**)&vh, g_vh);
    cudaGetSymbolAddress((void**)&k2h, g_k2h);
    cudaGetSymbolAddress((void**)&v2h, g_v2h);
    cudaGetSymbolAddress((void**)&k4h, g_k4h);
    cudaGetSymbolAddress((void**)&v4h, g_v4h);
    cudaGetSymbolAddress((void**)&ctx, g_ctx);
    cudaGetSymbolAddress((void**)&ctxh, g_ctxh);
    cudaGetSymbolAddress((void**)&wch, g_wch);
    cudaGetSymbolAddress((void**)&xh, g_xh);

    const int O_WQ = 0, O_WDKV = 589824, O_WUK1 = 786432, O_WUV1 = 983040;
    const int O_WUK2 = 1179648, O_WUV2 = 1376256, O_WUK4 = 1572864, O_WUV4 = 1769472;
    const int O_WOUT = 1966080;

    CvtArgs ca;
    ca.src[0] = wq;   ca.dst[0] = wch + O_WQ;   ca.n[0] = 589824;
    ca.src[1] = wdkv; ca.dst[1] = wch + O_WDKV; ca.n[1] = 196608;
    ca.src[2] = wuk1; ca.dst[2] = wch + O_WUK1; ca.n[2] = 196608;
    ca.src[3] = wuv1; ca.dst[3] = wch + O_WUV1; ca.n[3] = 196608;
    ca.src[4] = wuk2; ca.dst[4] = wch + O_WUK2; ca.n[4] = 196608;
    ca.src[5] = wuv2; ca.dst[5] = wch + O_WUV2; ca.n[5] = 196608;
    ca.src[6] = wuk4; ca.dst[6] = wch + O_WUK4; ca.n[6] = 196608;
    ca.src[7] = wuv4; ca.dst[7] = wch + O_WUV4; ca.n[7] = 196608;
    ca.src[8] = wout; ca.dst[8] = wch + O_WOUT; ca.n[8] = 589824;
    ca.src[9] = x;    ca.dst[9] = xh;           ca.n[9] = Bv * Tv * DMv;

    const int GEMM_SMEM = 26880 * 4;           // 107,520 B
    const int ATT_SMEM = ATT_SMEM_WORDS * 4;   // 56,320 B
    cudaFuncSetAttribute(gemm_fp16, cudaFuncAttributeMaxDynamicSharedMemorySize,
                         GEMM_SMEM);
    cudaFuncSetAttribute(attn_fused, cudaFuncAttributeMaxDynamicSharedMemorySize,
                         ATT_SMEM);

    const int MQ = Bv * Tv;  // 9216

    cvtw_kernel<<<512, 256>>>(ca);

    gemm_fp16<<<dim3(6, 72), 256, GEMM_SMEM>>>(xh, wch + O_WQ, nullptr, nullptr,
                                               qh, nullptr, MQ, DMv, DMv, 1);
    gemm_fp16<<<dim3(2, 72), 256, GEMM_SMEM>>>(xh, wch + O_WDKV, nullptr, nullptr,
                                               lath, nullptr, MQ, LDv, DMv, 1);

    gemm_fp16<<<dim3(6, 72, 2), 256, GEMM_SMEM>>>(lath, wch + O_WUK1, wch + O_WUV1,
                                                  nullptr, kh, vh, MQ, DMv, LDv, 1);

    pool_kernel<<<(Bv * 144 * LDv + 255) / 256, 256>>>(lath, lp2h, 2, 12, Bv * 144 * LDv);
    gemm_fp16<<<dim3(6, 18, 2), 256, GEMM_SMEM>>>(lp2h, wch + O_WUK2, wch + O_WUV2,
                                                  nullptr, k2h, v2h, Bv * 144, DMv, LDv, 1);

    pool_kernel<<<(Bv * 36 * LDv + 255) / 256, 256>>>(lath, lp4h, 4, 6, Bv * 36 * LDv);
    gemm_fp16<<<dim3(6, 5, 2), 256, GEMM_SMEM>>>(lp4h, wch + O_WUK4, wch + O_WUV4,
                                                 nullptr, k4h, v4h, Bv * 36, DMv, LDv, 1);

    attn_fused<<<dim3(5, NHv, Bv), 256, ATT_SMEM>>>(qh, kh, vh, k2h, v2h, k4h, v4h,
                                                    tbl1, tbl2, tbl4, ctx);

    cvtctx_kernel<<<(MQ * DMv / 4 + 255) / 256, 256>>>(ctx, ctxh, MQ * DMv / 4);

    gemm_fp16<<<dim3(6, 72), 256, GEMM_SMEM>>>(ctxh, wch + O_WOUT, nullptr, bout,
                                               (float*)d_out, nullptr, MQ, DMv, DMv, 0);
}

// round 11
// speedup vs baseline: 2.3382x; 1.2127x over previous
#include <cuda_runtime.h>
#include <cuda_fp16.h>
#include <cstdint>
#include <cstddef>

#define Bv 16
#define Tv 576
#define NHv 12
#define HDv 64
#define DMv 768
#define LDv 256

// ---------------- scratch (static device allocations; no cudaMalloc) ---------
__device__ __half g_qh[Bv * Tv * DMv];
__device__ __half g_lath[Bv * Tv * LDv];
__device__ __half g_lp2h[Bv * 144 * LDv];
__device__ __half g_lp4h[Bv * 36 * LDv];
__device__ __half g_kh[Bv * Tv * DMv];
__device__ __half g_vh[Bv * Tv * DMv];
__device__ __half g_k2h[Bv * 144 * DMv];
__device__ __half g_v2h[Bv * 144 * DMv];
__device__ __half g_k4h[Bv * 36 * DMv];
__device__ __half g_v4h[Bv * 36 * DMv];
__device__ float g_ctx[Bv * Tv * DMv];
__device__ __half g_ctxh[Bv * Tv * DMv];
__device__ __half g_wch[2555904];        // fp16 weights
__device__ __half g_xh[Bv * Tv * DMv];   // fp16 x

// ---------------- helpers -----------------------------------------------------
__device__ __forceinline__ uint32_t pack_f16x2(float lo, float hi) {
    uint32_t u;
    asm("cvt.rn.f16x2.f32 %0, %1, %2;" : "=r"(u) : "f"(hi), "f"(lo));
    return u;
}

__device__ __forceinline__ void mma_f16(float& c0, float& c1, float& c2, float& c3,
                                        uint32_t a0, uint32_t a1, uint32_t a2, uint32_t a3,
                                        uint32_t b0, uint32_t b1) {
    asm volatile(
        "mma.sync.aligned.m16n8k16.row.col.f32.f16.f16.f32 "
        "{%0,%1,%2,%3}, {%4,%5,%6,%7}, {%8,%9}, {%0,%1,%2,%3};"
        : "+f"(c0), "+f"(c1), "+f"(c2), "+f"(c3)
        : "r"(a0), "r"(a1), "r"(a2), "r"(a3), "r"(b0), "r"(b1));
}

__device__ __forceinline__ void ldsm4(uint32_t& r0, uint32_t& r1, uint32_t& r2,
                                      uint32_t& r3, uint32_t addr) {
    asm volatile("ldmatrix.sync.aligned.m8n8.x4.shared.b16 {%0,%1,%2,%3}, [%4];"
                 : "=r"(r0), "=r"(r1), "=r"(r2), "=r"(r3) : "r"(addr));
}
__device__ __forceinline__ void ldsm4t(uint32_t& r0, uint32_t& r1, uint32_t& r2,
                                       uint32_t& r3, uint32_t addr) {
    asm volatile("ldmatrix.sync.aligned.m8n8.x4.trans.shared.b16 {%0,%1,%2,%3}, [%4];"
                 : "=r"(r0), "=r"(r1), "=r"(r2), "=r"(r3) : "r"(addr));
}

__device__ __forceinline__ void cpa16(uint32_t dst, const void* src) {
    asm volatile("cp.async.cg.shared.global [%0], [%1], 16;" :: "r"(dst), "l"(src));
}
__device__ __forceinline__ void cpa16z(uint32_t dst, const void* src, int pred) {
    asm volatile(
        "{\n\t.reg .pred p;\n\tsetp.ne.b32 p, %2, 0;\n\t"
        "@p cp.async.cg.shared.global [%0], [%1], 16;\n\t"
        "@!p cp.async.cg.shared.global [%0], [%1], 16, 0;\n\t}"
        :: "r"(dst), "l"(src), "r"(pred));
}
__device__ __forceinline__ void cp_commit() { asm volatile("cp.async.commit_group;"); }
__device__ __forceinline__ void cp_wait0() { asm volatile("cp.async.wait_group 0;"); }
__device__ __forceinline__ void cp_wait1() { asm volatile("cp.async.wait_group 1;"); }

// ---------------- fp16 pre-conversion, vectorized ------------------------------
struct CvtArgs {
    const float* src[10];
    __half* dst[10];
    int n4[10];   // element count / 4
};
__global__ void cvtw_kernel(CvtArgs a) {
    int gid = blockIdx.x * blockDim.x + threadIdx.x;
    int stride = gridDim.x * blockDim.x;
#pragma unroll
    for (int s = 0; s < 10; s++) {
        const float4* sp = (const float4*)a.src[s];
        uint2* dp = (uint2*)a.dst[s];
        int n = a.n4[s];
        for (int i = gid; i < n; i += stride) {
            float4 v = sp[i];
            uint2 o;
            o.x = pack_f16x2(v.x, v.y);
            o.y = pack_f16x2(v.z, v.w);
            dp[i] = o;
        }
    }
}

// ---------------- ctx fp32 -> fp16 ---------------------------------------------
__global__ void cvtctx_kernel(const float* __restrict__ src,
                              __half* __restrict__ dst, int n4) {
    int i = blockIdx.x * blockDim.x + threadIdx.x;
    if (i >= n4) return;
    float4 v = *(const float4*)(src + i * 4);
    uint2 o;
    o.x = pack_f16x2(v.x, v.y);
    o.y = pack_f16x2(v.z, v.w);
    *(uint2*)(dst + i * 4) = o;
}

// ---------------- fp16 tensor-core GEMM, 3-stage cp.async, BK=64 ---------------
__global__ __launch_bounds__(256, 2) void gemm_fp16(
    const __half* __restrict__ A, const __half* __restrict__ Bw,
    const __half* __restrict__ B2, const float* __restrict__ bias,
    void* __restrict__ Cv, void* __restrict__ C2v,
    int M, int N, int K, int fp16out) {
    if (blockIdx.z == 1) { Bw = B2; Cv = C2v; }

    extern __shared__ uint32_t sm[];
    const int bm = blockIdx.y * 128;
    const int bn = blockIdx.x * 128;
    const int tid = threadIdx.x;
    const int lane = tid & 31;
    const int warp = tid >> 5;
    const int wm = (warp & 1) * 64;
    const int wn = (warp >> 1) * 32;
    const int g = lane >> 2;
    const int t = lane & 3;
    const int nk = K >> 6;
    uint32_t sb = (uint32_t)__cvta_generic_to_shared(sm);

    auto issue = [&](int it) {
        int buf = it % 3;
        int k0 = it << 6;
#pragma unroll
        for (int u = 0; u < 4; u++) {
            int idx = u * 256 + tid;
            int r = idx >> 3;
            int ch = idx & 7;
            int pred = (bm + r) < M;
            cpa16z(sb + (buf * 4608 + r * 36 + ch * 4) * 4,
                   A + (size_t)(bm + r) * K + k0 + ch * 8, pred);
        }
#pragma unroll
        for (int u = 0; u < 4; u++) {
            int idx = u * 256 + tid;
            int kk = idx >> 4;
            int ch = idx & 15;
            cpa16(sb + (13824 + buf * 4352 + kk * 68 + ch * 4) * 4,
                  Bw + (size_t)(k0 + kk) * N + bn + ch * 8);
        }
        cp_commit();
    };

    float c[4][4][4];
#pragma unroll
    for (int mt = 0; mt < 4; mt++)
#pragma unroll
        for (int nt = 0; nt < 4; nt++)
#pragma unroll
            for (int r = 0; r < 4; r++) c[mt][nt][r] = 0.f;

    issue(0);
    issue(1);

    const uint32_t aB = sb + (((wm + (lane & 15)) * 36) + (lane >> 4) * 4) * 4;
    const uint32_t bB = sb + 13824 * 4 +
        (((((lane >> 3) & 1) * 8 + (lane & 7)) * 68) + (wn >> 1) + (lane >> 4) * 4) * 4;

    for (int it = 0; it < nk; it++) {
        if (it + 1 < nk) cp_wait1(); else cp_wait0();
        __syncthreads();
        if (it + 2 < nk) issue(it + 2);
        const uint32_t aOff = (uint32_t)((it % 3) * 4608 * 4);
        const uint32_t bOff = (uint32_t)((it % 3) * 4352 * 4);
#pragma unroll
        for (int ks = 0; ks < 4; ks++) {
            uint32_t af[4][4];
#pragma unroll
            for (int mt = 0; mt < 4; mt++)
                ldsm4(af[mt][0], af[mt][1], af[mt][2], af[mt][3],
                      aB + aOff + (uint32_t)((mt * 16 * 36 + ks * 8) * 4));
            uint32_t bf[4][2];
#pragma unroll
            for (int nh = 0; nh < 2; nh++) {
                uint32_t v0, v1, v2, v3;
                ldsm4t(v0, v1, v2, v3,
                       bB + bOff + (uint32_t)((ks * 16 * 68 + nh * 8) * 4));
                bf[nh * 2][0] = v0; bf[nh * 2][1] = v1;
                bf[nh * 2 + 1][0] = v2; bf[nh * 2 + 1][1] = v3;
            }
#pragma unroll
            for (int mt = 0; mt < 4; mt++)
#pragma unroll
                for (int nt = 0; nt < 4; nt++)
                    mma_f16(c[mt][nt][0], c[mt][nt][1], c[mt][nt][2], c[mt][nt][3],
                            af[mt][0], af[mt][1], af[mt][2], af[mt][3],
                            bf[nt][0], bf[nt][1]);
        }
        __syncthreads();
    }

#pragma unroll
    for (int mt = 0; mt < 4; mt++) {
#pragma unroll
        for (int nt = 0; nt < 4; nt++) {
            int row0 = bm + wm + mt * 16 + g;
            int col = bn + wn + nt * 8 + t * 2;
            if (fp16out) {
                __half* Ch = (__half*)Cv;
                uint32_t h01 = pack_f16x2(c[mt][nt][0], c[mt][nt][1]);
                uint32_t h23 = pack_f16x2(c[mt][nt][2], c[mt][nt][3]);
                if (row0 < M) *(uint32_t*)(Ch + (size_t)row0 * N + col) = h01;
                if (row0 + 8 < M) *(uint32_t*)(Ch + (size_t)(row0 + 8) * N + col) = h23;
            } else {
                float* C = (float*)Cv;
                float b0 = bias ? bias[col] : 0.f;
                float b1 = bias ? bias[col + 1] : 0.f;
                if (row0 < M)
                    *(float2*)(C + (size_t)row0 * N + col) =
                        make_float2(c[mt][nt][0] + b0, c[mt][nt][1] + b1);
                if (row0 + 8 < M)
                    *(float2*)(C + (size_t)(row0 + 8) * N + col) =
                        make_float2(c[mt][nt][2] + b0, c[mt][nt][3] + b1);
            }
        }
    }
}

// ---------------- exact sxs mean pooling (fp16 in/out, fp32 sum) ---------------
__global__ void pool_kernel(const __half* __restrict__ lat, __half* __restrict__ out,
                            int s, int g, int n) {
    int idx = blockIdx.x * blockDim.x + threadIdx.x;
    if (idx >= n) return;
    int c = idx & (LDv - 1);
    int rest = idx >> 8;
    int cell = rest % (g * g);
    int b = rest / (g * g);
    int gh = cell / g, gw = cell % g;
    float sum = 0.f;
    for (int i = 0; i < s; i++)
        for (int j = 0; j < s; j++)
            sum += __half2float(
                lat[((size_t)(b * Tv) + (gh * s + i) * 24 + (gw * s + j)) * LDv + c]);
    out[idx] = __float2half(sum / (float)(s * s));
}

// ---------------- fused 3-scale fp16 flash attention, s=1 fast-bias path -------
// For s=1 tiles (vt<9), the rel-pos index separates: idx = base_k + qoff_q with
// base_k = (23-kh)*47 + (23-kw) precomputed per key (ints aliased into khcs),
// qoff = qh*47 + qw a per-thread constant. No trunc, no mask (9*64 == Kt).
#define ATT_SMEM_WORDS 14080

__global__ __launch_bounds__(256, 2) void attn_fused(
    const __half* __restrict__ qbuf,
    const __half* __restrict__ k1, const __half* __restrict__ v1,
    const __half* __restrict__ k2, const __half* __restrict__ v2,
    const __half* __restrict__ k4, const __half* __restrict__ v4,
    const float* __restrict__ tbl1, const float* __restrict__ tbl2,
    const float* __restrict__ tbl4, float* __restrict__ ctx) {
    extern __shared__ uint32_t smu[];
    float* khcs = (float*)(smu + 13824);   // [2][64] floats (s>1) / ints (s=1)
    float* kwcs = khcs + 128;              // [2][64]
    int* ibase = (int*)khcs;               // alias for s=1 integer bases
    uint32_t sb = (uint32_t)__cvta_generic_to_shared(smu);

    const int b = blockIdx.z;
    const int h = blockIdx.y;
    const int q0 = blockIdx.x * 128;
    const int tid = threadIdx.x;
    const int lane = tid & 31;
    const int w = tid >> 5;
    const int g = lane >> 2;
    const int t = lane & 3;
    const int lr0 = w * 16 + g;
    const int lr1 = lr0 + 8;

    auto issue_kv = [&](int vt) {
        const __half *kb, *vb;
        int Kt, kt;
        if (vt < 9) {
            kb = k1 + (size_t)b * 576 * DMv + h * HDv;
            vb = v1 + (size_t)b * 576 * DMv + h * HDv;
            Kt = 576; kt = vt;
        } else if (vt < 12) {
            kb = k2 + (size_t)b * 144 * DMv + h * HDv;
            vb = v2 + (size_t)b * 144 * DMv + h * HDv;
            Kt = 144; kt = vt - 9;
        } else {
            kb = k4 + (size_t)b * 36 * DMv + h * HDv;
            vb = v4 + (size_t)b * 36 * DMv + h * HDv;
            Kt = 36; kt = 0;
        }
        int buf = vt & 1;
#pragma unroll
        for (int u = 0; u < 2; u++) {
            int idx = u * 256 + tid;
            int r = idx >> 3;
            int c8 = (idx & 7) << 3;
            int kg = kt * 64 + r;
            int pred = kg < Kt;
            cpa16z(sb + (buf * 2304 + r * 36 + (c8 >> 1)) * 4,
                   kb + (size_t)kg * DMv + c8, pred);
            cpa16z(sb + (4608 + buf * 2304 + r * 36 + (c8 >> 1)) * 4,
                   vb + (size_t)kg * DMv + c8, pred);
        }
    };

    const __half* qsrc = qbuf + (size_t)(b * Tv) * DMv + h * HDv;
#pragma unroll
    for (int u = 0; u < 4; u++) {
        int idx = u * 256 + tid;
        int r = idx >> 3;
        int c8 = (idx & 7) << 3;
        int row = q0 + r;
        if (row > Tv - 1) row = Tv - 1;
        *(uint4*)&smu[9216 + r * 36 + (c8 >> 1)] =
            *(const uint4*)(qsrc + (size_t)row * DMv + c8);
    }
    issue_kv(0);
    cp_commit();
    __syncthreads();

    uint32_t qf[4][4];
#pragma unroll
    for (int ks = 0; ks < 4; ks++) {
        qf[ks][0] = smu[9216 + lr0 * 36 + ks * 8 + t];
        qf[ks][1] = smu[9216 + lr1 * 36 + ks * 8 + t];
        qf[ks][2] = smu[9216 + lr0 * 36 + ks * 8 + t + 4];
        qf[ks][3] = smu[9216 + lr1 * 36 + ks * 8 + t + 4];
    }

    float o[8][4];
#pragma unroll
    for (int nt = 0; nt < 8; nt++)
#pragma unroll
        for (int r = 0; r < 4; r++) o[nt][r] = 0.f;
    float l0 = 0.f, l1 = 0.f;

    const float scl = 0.125f;
    const int qi0 = q0 + lr0;
    const int qi1 = q0 + lr1;
    const int qc0 = qi0 < Tv ? qi0 : Tv - 1;
    const int qc1 = qi1 < Tv ? qi1 : Tv - 1;
    const int qh0i = qc0 / 24, qw0i = qc0 % 24;
    const int qh1i = qc1 / 24, qw1i = qc1 % 24;
    const int qoff0 = qh0i * 47 + qw0i;
    const int qoff1 = qh1i * 47 + qw1i;
    const float qh0 = (float)qh0i, qw0 = (float)qw0i;
    const float qh1 = (float)qh1i, qw1 = (float)qw1i;
    float* c0p = ctx + ((size_t)(b * Tv + qc0)) * DMv + h * HDv;
    float* c1p = ctx + ((size_t)(b * Tv + qc1)) * DMv + h * HDv;

    const uint32_t krow = sb + (((lane & 7) * 36) + ((lane >> 3) << 2)) * 4;
    const uint32_t vrow = sb + 4608 * 4 +
        (((((lane >> 3) & 1) * 8 + (lane & 7)) * 36) + ((lane >> 4) << 2)) * 4;

    for (int vt = 0; vt < 13; vt++) {
        int seg, Kt, kt, gw_, s_, tw_;
        const float* tb;
        if (vt < 9)       { seg = 0; Kt = 576; kt = vt;      gw_ = 24; s_ = 1; tw_ = 47; tb = tbl1 + h * (47 * 47); }
        else if (vt < 12) { seg = 1; Kt = 144; kt = vt - 9;  gw_ = 12; s_ = 2; tw_ = 23; tb = tbl2 + h * (47 * 23); }
        else              { seg = 2; Kt = 36;  kt = 0;       gw_ = 6;  s_ = 4; tw_ = 11; tb = tbl4 + h * (47 * 11); }
        const float hctr = 0.5f * (float)(s_ - 1);
        const int buf = vt & 1;

        cp_wait0();
        if (tid < 64) {
            int kg = kt * 64 + tid;
            if (vt < 9) {
                ibase[buf * 64 + tid] = (23 - kg / 24) * 47 + (23 - kg % 24);
            } else if (kg < Kt) {
                khcs[buf * 64 + tid] = (float)((kg / gw_) * s_) + hctr;
                kwcs[buf * 64 + tid] = (float)((kg % gw_) * s_) + hctr;
            }
        }
        __syncthreads();
        if (vt + 1 < 13) { issue_kv(vt + 1); cp_commit(); }

        const uint32_t kbase = krow + (buf * 2304) * 4;
        const uint32_t vbase = vrow + (buf * 2304) * 4;

        uint32_t pA[8], pB[8];
        if (vt < 9) {
            // ---- fast s=1 path: separable integer bias index, no masking ----
            const int* ib = ibase + buf * 64;
#pragma unroll
            for (int nt = 0; nt < 8; nt++) {
                uint32_t r0, r1, r2, r3, r4, r5, r6, r7;
                ldsm4(r0, r1, r2, r3, kbase + (nt * 8 * 36) * 4);
                ldsm4(r4, r5, r6, r7, kbase + (nt * 8 * 36) * 4 + 64);
                float s0 = 0.f, s1 = 0.f, s2 = 0.f, s3 = 0.f;
                mma_f16(s0, s1, s2, s3, qf[0][0], qf[0][1], qf[0][2], qf[0][3], r0, r1);
                mma_f16(s0, s1, s2, s3, qf[1][0], qf[1][1], qf[1][2], qf[1][3], r2, r3);
                mma_f16(s0, s1, s2, s3, qf[2][0], qf[2][1], qf[2][2], qf[2][3], r4, r5);
                mma_f16(s0, s1, s2, s3, qf[3][0], qf[3][1], qf[3][2], qf[3][3], r6, r7);

                int lc = nt * 8 + t * 2;
                int bA = ib[lc], bB = ib[lc + 1];
                float p0 = __expf(s0 * scl + __ldg(tb + bA + qoff0));
                float p1 = __expf(s1 * scl + __ldg(tb + bB + qoff0));
                float p2 = __expf(s2 * scl + __ldg(tb + bA + qoff1));
                float p3 = __expf(s3 * scl + __ldg(tb + bB + qoff1));
                l0 += p0 + p1;
                l1 += p2 + p3;
                pA[nt] = pack_f16x2(p0, p1);
                pB[nt] = pack_f16x2(p2, p3);
            }
        } else {
            // ---- general path (s = 2, 4): float centers + trunc ----
#pragma unroll
            for (int nt = 0; nt < 8; nt++) {
                uint32_t r0, r1, r2, r3, r4, r5, r6, r7;
                ldsm4(r0, r1, r2, r3, kbase + (nt * 8 * 36) * 4);
                ldsm4(r4, r5, r6, r7, kbase + (nt * 8 * 36) * 4 + 64);
                float s0 = 0.f, s1 = 0.f, s2 = 0.f, s3 = 0.f;
                mma_f16(s0, s1, s2, s3, qf[0][0], qf[0][1], qf[0][2], qf[0][3], r0, r1);
                mma_f16(s0, s1, s2, s3, qf[1][0], qf[1][1], qf[1][2], qf[1][3], r2, r3);
                mma_f16(s0, s1, s2, s3, qf[2][0], qf[2][1], qf[2][2], qf[2][3], r4, r5);
                mma_f16(s0, s1, s2, s3, qf[3][0], qf[3][1], qf[3][2], qf[3][3], r6, r7);

                int lc = nt * 8 + t * 2;
                int kg = kt * 64 + lc;
                float p0 = 0.f, p1 = 0.f, p2 = 0.f, p3 = 0.f;
                if (kg < Kt) {
                    float khcA = khcs[buf * 64 + lc], kwcA = kwcs[buf * 64 + lc];
                    float khcB = khcs[buf * 64 + lc + 1], kwcB = kwcs[buf * 64 + lc + 1];
                    int rh0a = (int)(qh0 - khcA) + 23, rw0a = (int)(qw0 - kwcA) + (gw_ - 1);
                    int rh0b = (int)(qh0 - khcB) + 23, rw0b = (int)(qw0 - kwcB) + (gw_ - 1);
                    int rh1a = (int)(qh1 - khcA) + 23, rw1a = (int)(qw1 - kwcA) + (gw_ - 1);
                    int rh1b = (int)(qh1 - khcB) + 23, rw1b = (int)(qw1 - kwcB) + (gw_ - 1);
                    p0 = __expf(s0 * scl + __ldg(&tb[rh0a * tw_ + rw0a]));
                    p1 = __expf(s1 * scl + __ldg(&tb[rh0b * tw_ + rw0b]));
                    p2 = __expf(s2 * scl + __ldg(&tb[rh1a * tw_ + rw1a]));
                    p3 = __expf(s3 * scl + __ldg(&tb[rh1b * tw_ + rw1b]));
                }
                l0 += p0 + p1;
                l1 += p2 + p3;
                pA[nt] = pack_f16x2(p0, p1);
                pB[nt] = pack_f16x2(p2, p3);
            }
        }

#pragma unroll
        for (int ks = 0; ks < 4; ks++) {
            uint32_t a0 = pA[2 * ks], a1 = pB[2 * ks];
            uint32_t a2 = pA[2 * ks + 1], a3 = pB[2 * ks + 1];
#pragma unroll
            for (int p = 0; p < 4; p++) {
                uint32_t v0, v1, v2, v3;
                ldsm4t(v0, v1, v2, v3, vbase + (ks * 16 * 36 + p * 8) * 4);
                mma_f16(o[2 * p][0], o[2 * p][1], o[2 * p][2], o[2 * p][3],
                        a0, a1, a2, a3, v0, v1);
                mma_f16(o[2 * p + 1][0], o[2 * p + 1][1], o[2 * p + 1][2], o[2 * p + 1][3],
                        a0, a1, a2, a3, v2, v3);
            }
        }

        if (vt == 8 || vt == 11 || vt == 12) {
            float L0 = l0, L1 = l1;
            L0 += __shfl_xor_sync(0xffffffffu, L0, 1);
            L0 += __shfl_xor_sync(0xffffffffu, L0, 2);
            L1 += __shfl_xor_sync(0xffffffffu, L1, 1);
            L1 += __shfl_xor_sync(0xffffffffu, L1, 2);
            float inv0 = 1.f / (3.f * L0);
            float inv1 = 1.f / (3.f * L1);
            if (vt == 8) {
#pragma unroll
                for (int nt = 0; nt < 8; nt++) {
                    int col = nt * 8 + t * 2;
                    if (qi0 < Tv) {
                        c0p[col] = o[nt][0] * inv0;
                        c0p[col + 1] = o[nt][1] * inv0;
                    }
                    if (qi1 < Tv) {
                        c1p[col] = o[nt][2] * inv1;
                        c1p[col + 1] = o[nt][3] * inv1;
                    }
                }
            } else {
#pragma unroll
                for (int nt = 0; nt < 8; nt++) {
                    int col = nt * 8 + t * 2;
                    if (qi0 < Tv) {
                        c0p[col] += o[nt][0] * inv0;
                        c0p[col + 1] += o[nt][1] * inv0;
                    }
                    if (qi1 < Tv) {
                        c1p[col] += o[nt][2] * inv1;
                        c1p[col + 1] += o[nt][3] * inv1;
                    }
                }
            }
#pragma unroll
            for (int nt = 0; nt < 8; nt++)
#pragma unroll
                for (int r = 0; r < 4; r++) o[nt][r] = 0.f;
            l0 = 0.f;
            l1 = 0.f;
        }
    }
}

// ---------------- launch ------------------------------------------------------
extern "C" void kernel_launch(void* const* d_in, const int* in_sizes, int n_in,
                              void* d_out, int out_size) {
    const float* x    = (const float*)d_in[0];
    const float* wq   = (const float*)d_in[1];
    const float* wdkv = (const float*)d_in[2];
    const float* wuk1 = (const float*)d_in[3];
    const float* wuk2 = (const float*)d_in[4];
    const float* wuk4 = (const float*)d_in[5];
    const float* wuv1 = (const float*)d_in[6];
    const float* wuv2 = (const float*)d_in[7];
    const float* wuv4 = (const float*)d_in[8];
    const float* wout = (const float*)d_in[9];
    const float* bout = (const float*)d_in[10];
    const float* tbl1 = (const float*)d_in[11];
    const float* tbl2 = (const float*)d_in[12];
    const float* tbl4 = (const float*)d_in[13];

    float* ctx;
    __half *qh, *lath, *lp2h, *lp4h, *kh, *vh, *k2h, *v2h, *k4h, *v4h, *wch, *xh, *ctxh;
    cudaGetSymbolAddress((void**)&qh, g_qh);
    cudaGetSymbolAddress((void**)&lath, g_lath);
    cudaGetSymbolAddress((void**)&lp2h, g_lp2h);
    cudaGetSymbolAddress((void**)&lp4h, g_lp4h);
    cudaGetSymbolAddress((void**)&kh, g_kh);
    cudaGetSymbolAddress((void**)&vh, g_vh);
    cudaGetSymbolAddress((void**)&k2h, g_k2h);
    cudaGetSymbolAddress((void**)&v2h, g_v2h);
    cudaGetSymbolAddress((void**)&k4h, g_k4h);
    cudaGetSymbolAddress((void**)&v4h, g_v4h);
    cudaGetSymbolAddress((void**)&ctx, g_ctx);
    cudaGetSymbolAddress((void**)&ctxh, g_ctxh);
    cudaGetSymbolAddress((void**)&wch, g_wch);
    cudaGetSymbolAddress((void**)&xh, g_xh);

    const int O_WQ = 0, O_WDKV = 589824, O_WUK1 = 786432, O_WUV1 = 983040;
    const int O_WUK2 = 1179648, O_WUV2 = 1376256, O_WUK4 = 1572864, O_WUV4 = 1769472;
    const int O_WOUT = 1966080;

    CvtArgs ca;
    ca.src[0] = wq;   ca.dst[0] = wch + O_WQ;   ca.n4[0] = 589824 / 4;
    ca.src[1] = wdkv; ca.dst[1] = wch + O_WDKV; ca.n4[1] = 196608 / 4;
    ca.src[2] = wuk1; ca.dst[2] = wch + O_WUK1; ca.n4[2] = 196608 / 4;
    ca.src[3] = wuv1; ca.dst[3] = wch + O_WUV1; ca.n4[3] = 196608 / 4;
    ca.src[4] = wuk2; ca.dst[4] = wch + O_WUK2; ca.n4[4] = 196608 / 4;
    ca.src[5] = wuv2; ca.dst[5] = wch + O_WUV2; ca.n4[5] = 196608 / 4;
    ca.src[6] = wuk4; ca.dst[6] = wch + O_WUK4; ca.n4[6] = 196608 / 4;
    ca.src[7] = wuv4; ca.dst[7] = wch + O_WUV4; ca.n4[7] = 196608 / 4;
    ca.src[8] = wout; ca.dst[8] = wch + O_WOUT; ca.n4[8] = 589824 / 4;
    ca.src[9] = x;    ca.dst[9] = xh;           ca.n4[9] = Bv * Tv * DMv / 4;

    const int GEMM_SMEM = 26880 * 4;           // 107,520 B
    const int ATT_SMEM = ATT_SMEM_WORDS * 4;   // 56,320 B
    cudaFuncSetAttribute(gemm_fp16, cudaFuncAttributeMaxDynamicSharedMemorySize,
                         GEMM_SMEM);
    cudaFuncSetAttribute(attn_fused, cudaFuncAttributeMaxDynamicSharedMemorySize,
                         ATT_SMEM);

    const int MQ = Bv * Tv;  // 9216

    cvtw_kernel<<<512, 256>>>(ca);

    gemm_fp16<<<dim3(6, 72), 256, GEMM_SMEM>>>(xh, wch + O_WQ, nullptr, nullptr,
                                               qh, nullptr, MQ, DMv, DMv, 1);
    gemm_fp16<<<dim3(2, 72), 256, GEMM_SMEM>>>(xh, wch + O_WDKV, nullptr, nullptr,
                                               lath, nullptr, MQ, LDv, DMv, 1);

    gemm_fp16<<<dim3(6, 72, 2), 256, GEMM_SMEM>>>(lath, wch + O_WUK1, wch + O_WUV1,
                                                  nullptr, kh, vh, MQ, DMv, LDv, 1);

    pool_kernel<<<(Bv * 144 * LDv + 255) / 256, 256>>>(lath, lp2h, 2, 12, Bv * 144 * LDv);
    gemm_fp16<<<dim3(6, 18, 2), 256, GEMM_SMEM>>>(lp2h, wch + O_WUK2, wch + O_WUV2,
                                                  nullptr, k2h, v2h, Bv * 144, DMv, LDv, 1);

    pool_kernel<<<(Bv * 36 * LDv + 255) / 256, 256>>>(lath, lp4h, 4, 6, Bv * 36 * LDv);
    gemm_fp16<<<dim3(6, 5, 2), 256, GEMM_SMEM>>>(lp4h, wch + O_WUK4, wch + O_WUV4,
                                                 nullptr, k4h, v4h, Bv * 36, DMv, LDv, 1);

    attn_fused<<<dim3(5, NHv, Bv), 256, ATT_SMEM>>>(qh, kh, vh, k2h, v2h, k4h, v4h,
                                                    tbl1, tbl2, tbl4, ctx);

    cvtctx_kernel<<<(MQ * DMv / 4 + 255) / 256, 256>>>(ctx, ctxh, MQ * DMv / 4);

    gemm_fp16<<<dim3(6, 72), 256, GEMM_SMEM>>>(ctxh, wch + O_WOUT, nullptr, bout,
                                               (float*)d_out, nullptr, MQ, DMv, DMv, 0);
}